// round 10
// baseline (speedup 1.0000x reference)
#include <cuda_runtime.h>
#include <cstdint>
#include <cstddef>

#define D_MODEL 1024
#define N_BATCH 4
#define N_SEQ   2048
#define N_HEADS 16
#define D_HEAD  64
#define N_ROWS  (N_BATCH * N_SEQ)   // 8192

// Scratch (device-global: no allocations allowed in kernel_launch).
__device__ float g_Q  [(size_t)N_ROWS * D_MODEL];  // plain, tf32-rounded
__device__ float g_K0 [(size_t)N_ROWS * D_MODEL];  // plain K, tf32-rounded
__device__ float g_V0 [(size_t)N_ROWS * D_MODEL];  // plain V, tf32-rounded
__device__ float g_Kp [(size_t)N_ROWS * D_MODEL];  // packed K per head chunk
__device__ float g_Vp [(size_t)N_ROWS * D_MODEL];  // packed V per (tile,h) block
__device__ float g_CTX[(size_t)N_ROWS * D_MODEL];  // plain, tf32-rounded
// tf32-pre-rounded plain copies of inputs
__device__ float g_qc[(size_t)N_ROWS * D_MODEL];
__device__ float g_kc[(size_t)N_ROWS * D_MODEL];
__device__ float g_vc[(size_t)N_ROWS * D_MODEL];
// weights: tf32-rounded, B-frag packed: Wp[n][kt:32][t:4][j:8] = W[kt*32+t+4j][n]
__device__ float g_Wqp[(size_t)D_MODEL * D_MODEL];
__device__ float g_Wkp[(size_t)D_MODEL * D_MODEL];
__device__ float g_Wvp[(size_t)D_MODEL * D_MODEL];
__device__ float g_Wop[(size_t)D_MODEL * D_MODEL];

// ---------------------------------------------------------------------------
// Helpers
// ---------------------------------------------------------------------------
__device__ __forceinline__ uint32_t f2tf32(float x) {
    uint32_t r;
    asm("cvt.rna.tf32.f32 %0, %1;" : "=r"(r) : "f"(x));
    return r;
}
__device__ __forceinline__ void mma_tf32(float d[4], const uint32_t a[4], const uint32_t b[2]) {
    asm volatile(
        "mma.sync.aligned.m16n8k8.row.col.f32.tf32.tf32.f32 "
        "{%0,%1,%2,%3}, {%4,%5,%6,%7}, {%8,%9}, {%0,%1,%2,%3};\n"
        : "+f"(d[0]), "+f"(d[1]), "+f"(d[2]), "+f"(d[3])
        : "r"(a[0]), "r"(a[1]), "r"(a[2]), "r"(a[3]), "r"(b[0]), "r"(b[1]));
}
__device__ __forceinline__ void cp16(uint32_t s, const void* g) {
    asm volatile("cp.async.cg.shared.global [%0], [%1], 16;\n" :: "r"(s), "l"(g));
}
__device__ __forceinline__ void cp_commit() { asm volatile("cp.async.commit_group;\n"); }
__device__ __forceinline__ void cp_wait0()  { asm volatile("cp.async.wait_group 0;\n"); }
__device__ __forceinline__ uint32_t smem_u32(const void* p) {
    uint32_t a;
    asm("{ .reg .u64 t; cvta.to.shared.u64 t, %1; cvt.u32.u64 %0, t; }"
        : "=r"(a) : "l"(p));
    return a;
}

// ---- packed f32x2 (Blackwell FFMA2 pipe) ----
__device__ __forceinline__ uint64_t pk2(float a, float b) {
    uint64_t r; asm("mov.b64 %0, {%1, %2};" : "=l"(r) : "f"(a), "f"(b)); return r;
}
__device__ __forceinline__ void upk2(uint64_t v, float& a, float& b) {
    asm("mov.b64 {%0, %1}, %2;" : "=f"(a), "=f"(b) : "l"(v));
}
__device__ __forceinline__ void upk2u(uint64_t v, uint32_t& a, uint32_t& b) {
    asm("mov.b64 {%0, %1}, %2;" : "=r"(a), "=r"(b) : "l"(v));
}
__device__ __forceinline__ uint64_t pk2u(uint32_t a, uint32_t b) {
    uint64_t r; asm("mov.b64 %0, {%1, %2};" : "=l"(r) : "r"(a), "r"(b)); return r;
}
__device__ __forceinline__ uint64_t pfma2(uint64_t a, uint64_t b, uint64_t c) {
    uint64_t r;
    asm("fma.rn.f32x2 %0, %1, %2, %3;" : "=l"(r) : "l"(a), "l"(b), "l"(c));
    return r;
}
__device__ __forceinline__ uint64_t padd2(uint64_t a, uint64_t b) {
    uint64_t r; asm("add.rn.f32x2 %0, %1, %2;" : "=l"(r) : "l"(a), "l"(b)); return r;
}
__device__ __forceinline__ uint64_t pmul2(uint64_t a, uint64_t b) {
    uint64_t r; asm("mul.rn.f32x2 %0, %1, %2;" : "=l"(r) : "l"(a), "l"(b)); return r;
}

// scalar exp(x) for x <= 0 with clamp (correction factors only). ~3e-6 rel.
__device__ __forceinline__ float fast_exp(float x) {
    float t = fmaxf(x * 1.4426950408889634f, -126.0f);
    float z = t + 12582912.0f;
    int  ki = __float_as_int(z) - 0x4B400000;
    float f = t - (z - 12582912.0f);
    float u = f * 0.6931471805599453f;
    float p = 1.0f + u * (1.0f + u * (0.5f + u * (0.16666667f +
              u * (0.041666668f + u * 0.008333334f))));
    return __int_as_float(__float_as_int(p) + (ki << 23));
}

// ---------------------------------------------------------------------------
// Fused input pre-round: z selects (q,k,v) pair. Coalesced both sides.
// ---------------------------------------------------------------------------
__global__ void __launch_bounds__(256)
cvt_in_kernel(const float4* i0, float4* o0, const float4* i1, float4* o1,
              const float4* i2, float4* o2, int n4)
{
    const float4* __restrict__ in  = (blockIdx.z == 0) ? i0 : (blockIdx.z == 1) ? i1 : i2;
    float4* __restrict__ out       = (blockIdx.z == 0) ? o0 : (blockIdx.z == 1) ? o1 : o2;
    for (int i = blockIdx.x * blockDim.x + threadIdx.x; i < n4;
         i += gridDim.x * blockDim.x) {
        float4 v = in[i];
        v.x = __uint_as_float(f2tf32(v.x));
        v.y = __uint_as_float(f2tf32(v.y));
        v.z = __uint_as_float(f2tf32(v.z));
        v.w = __uint_as_float(f2tf32(v.w));
        out[i] = v;
    }
}

// ---------------------------------------------------------------------------
// Fused weight transform (z selects 1 of 4 weights):
// Wp[n][kt*32 + t*8 + j] = round_tf32(W[kt*32 + t + 4*j][n])
// 32x32 smem tile transpose; coalesced both sides.
// ---------------------------------------------------------------------------
__global__ void __launch_bounds__(256)
cvt_wp_kernel(const float* W0, float* P0, const float* W1, float* P1,
              const float* W2, float* P2, const float* W3, float* P3)
{
    const float* __restrict__ W = (blockIdx.z == 0) ? W0 : (blockIdx.z == 1) ? W1
                                : (blockIdx.z == 2) ? W2 : W3;
    float* __restrict__ P       = (blockIdx.z == 0) ? P0 : (blockIdx.z == 1) ? P1
                                : (blockIdx.z == 2) ? P2 : P3;
    __shared__ float tle[32][33];
    const int tx = threadIdx.x & 31, ty = threadIdx.x >> 5;   // 32 x 8
    const int n0 = blockIdx.x * 32, k0 = blockIdx.y * 32;
    #pragma unroll
    for (int j = 0; j < 32; j += 8)
        tle[ty + j][tx] = W[(size_t)(k0 + ty + j) * D_MODEL + n0 + tx];
    __syncthreads();
    #pragma unroll
    for (int j = 0; j < 32; j += 8) {
        const int r = ty + j;                 // output n-row within tile
        const int p = tx;                     // packed position 0..31
        const int ksrc = (p >> 3) + 4 * (p & 7);   // t + 4*j
        P[(size_t)(n0 + r) * D_MODEL + k0 + p] =
            __uint_as_float(f2tf32(tle[ksrc][r]));
    }
}

// ---------------------------------------------------------------------------
// K pack: per 64-float head chunk, out[p] = in[(p%16)*4 + p/16].
// ---------------------------------------------------------------------------
__global__ void __launch_bounds__(256)
pack_k_kernel(const float* __restrict__ in, float* __restrict__ out)
{
    const int total2 = N_ROWS * D_MODEL / 2;
    for (int i = blockIdx.x * blockDim.x + threadIdx.x; i < total2;
         i += gridDim.x * blockDim.x) {
        const int o = i * 2, chunk = o >> 6, p = o & 63;   // p even
        const int dh = ((p & 15) << 2) + (p >> 4);
        const float* base = in + (size_t)chunk * 64;
        *(float2*)(out + (size_t)chunk * 64 + p) =
            make_float2(base[dh], base[dh + 4]);
    }
}

// ---------------------------------------------------------------------------
// V pack: one CTA per (tile=row/64, h).
// block[(rl&7)>>1 * 1024 + dh*16 + (rl>>3)*2 + (rl&1)] = V[tile*64+rl][h*64+dh]
// ---------------------------------------------------------------------------
__global__ void __launch_bounds__(256)
pack_v_kernel(const float* __restrict__ in, float* __restrict__ out)
{
    __shared__ float sm[64][65];
    const int tile = blockIdx.x, h = blockIdx.y;
    const int tid = threadIdx.x;
    const float* src = in + (size_t)tile * 64 * D_MODEL + h * 64;
    #pragma unroll
    for (int i = 0; i < 4; i++) {
        const int idx = tid + i * 256;
        const int rl = idx >> 4, c4 = (idx & 15) * 4;
        float4 v = *(const float4*)(src + (size_t)rl * D_MODEL + c4);
        sm[rl][c4] = v.x; sm[rl][c4 + 1] = v.y;
        sm[rl][c4 + 2] = v.z; sm[rl][c4 + 3] = v.w;
    }
    __syncthreads();
    float* dst = out + (size_t)(tile * 16 + h) * 4096;
    #pragma unroll
    for (int i = 0; i < 4; i++) {
        const int o = (tid + i * 256) * 4;
        float4 v;
        #pragma unroll
        for (int e = 0; e < 4; e++) {
            const int oo = o + e;
            const int tt = oo >> 10, dh = (oo >> 4) & 63, lo = oo & 15;
            const int rl = ((lo >> 1) << 3) + (tt << 1) + (lo & 1);
            ((float*)&v)[e] = sm[rl][dh];
        }
        *(float4*)(dst + o) = v;
    }
}

// ---------------------------------------------------------------------------
// GEMM: C[8192,1024] = A @ W + bias. A plain tf32 (round-3 loader);
// W packed Wp[n][kt][t:4][j:8] -> B-frag loads are 2x LDS.128 per nt per
// k-tile (was 16x LDS.32). Smem B rows stride 36 (phase-conflict-free for
// the 36g+8t pattern). Accumulation order identical to round 3.
// ---------------------------------------------------------------------------
#define BM 128
#define BN 128
#define BK 32
#define ASTR 36
#define BSTR2 36
#define A_BUF (BM * ASTR)      // 4608 floats
#define B_BUF (BN * BSTR2)     // 4608 floats
#define GEMM_SMEM ((2 * A_BUF + 2 * B_BUF) * 4)   // 73728 B

struct GemmSet { const float* A; const float* Wp; const float* bias; float* C; };

__global__ void __launch_bounds__(256)
gemm_bias_kernel(GemmSet s0, GemmSet s1, GemmSet s2, int round_out)
{
    const GemmSet& S = (blockIdx.z == 0) ? s0 : (blockIdx.z == 1) ? s1 : s2;
    const float* __restrict__ A    = S.A;
    const float* __restrict__ Wp   = S.Wp;
    const float* __restrict__ bias = S.bias;
    float* __restrict__ C          = S.C;

    extern __shared__ float smem[];
    float* As = smem;                       // [2][128][36]
    float* Bs = smem + 2 * A_BUF;           // [2][128][36]
    const uint32_t sA = smem_u32(As);
    const uint32_t sB = smem_u32(Bs);

    const int tid  = threadIdx.x;
    const int warp = tid >> 5, lane = tid & 31;
    const int g = lane >> 2, t = lane & 3;
    const int wm = warp >> 1, wn = warp & 1;
    const int m_base = wm * 32, n_base = wn * 64;
    const int cta_m = blockIdx.y * BM;
    const int cta_n = blockIdx.x * BN;

    float acc[2][8][4];
    #pragma unroll
    for (int i = 0; i < 2; i++)
        #pragma unroll
        for (int j = 0; j < 8; j++)
            #pragma unroll
            for (int e = 0; e < 4; e++) acc[i][j][e] = 0.f;

    auto issue_loads = [&](int kt, int buf) {
        const float* Ag = A + (size_t)cta_m * D_MODEL + kt * BK;
        #pragma unroll
        for (int i = 0; i < 4; i++) {           // A: 128 rows x 8 chunks
            int idx = tid + i * 256;
            int r = idx >> 3, c = (idx & 7) * 4;
            cp16(sA + (uint32_t)(buf * A_BUF + r * ASTR + c) * 4,
                 Ag + (size_t)r * D_MODEL + c);
        }
        const float* Bg = Wp + (size_t)cta_n * D_MODEL + kt * BK;
        #pragma unroll
        for (int i = 0; i < 4; i++) {           // B: 128 n-rows x 8 chunks
            int idx = tid + i * 256;
            int r = idx >> 3, c = (idx & 7) * 4;
            cp16(sB + (uint32_t)(buf * B_BUF + r * BSTR2 + c) * 4,
                 Bg + (size_t)r * D_MODEL + c);
        }
        cp_commit();
    };

    issue_loads(0, 0);

    const int KT = D_MODEL / BK;  // 32
    for (int kt = 0; kt < KT; kt++) {
        cp_wait0();
        __syncthreads();
        if (kt + 1 < KT) issue_loads(kt + 1, (kt + 1) & 1);

        const float* Ab = As + (kt & 1) * A_BUF;
        const float* Bb = Bs + (kt & 1) * B_BUF;

        // A fragments (plain scalar loads, as round 3)
        uint32_t af[4][2][4];   // [kk][mt][4]
        #pragma unroll
        for (int kk = 0; kk < 4; kk++) {
            const int k0 = kk * 8;
            #pragma unroll
            for (int mt = 0; mt < 2; mt++) {
                const int m0 = m_base + mt * 16;
                af[kk][mt][0] = __float_as_uint(Ab[(m0 + g)     * ASTR + k0 + t]);
                af[kk][mt][1] = __float_as_uint(Ab[(m0 + g + 8) * ASTR + k0 + t]);
                af[kk][mt][2] = __float_as_uint(Ab[(m0 + g)     * ASTR + k0 + t + 4]);
                af[kk][mt][3] = __float_as_uint(Ab[(m0 + g + 8) * ASTR + k0 + t + 4]);
            }
        }
        // B fragments: per nt one 32B packed read (2x LDS.128)
        #pragma unroll
        for (int nt = 0; nt < 8; nt++) {
            const float4* bp = (const float4*)
                (Bb + (n_base + nt * 8 + g) * BSTR2 + t * 8);
            float4 y0 = bp[0], y1 = bp[1];
            const uint32_t pw[8] = {
                __float_as_uint(y0.x), __float_as_uint(y0.y),
                __float_as_uint(y0.z), __float_as_uint(y0.w),
                __float_as_uint(y1.x), __float_as_uint(y1.y),
                __float_as_uint(y1.z), __float_as_uint(y1.w)};
            #pragma unroll
            for (int kk = 0; kk < 4; kk++) {
                uint32_t b2[2] = {pw[2 * kk], pw[2 * kk + 1]};
                mma_tf32(acc[0][nt], af[kk][0], b2);
                mma_tf32(acc[1][nt], af[kk][1], b2);
            }
        }
    }

    #pragma unroll
    for (int mt = 0; mt < 2; mt++) {
        #pragma unroll
        for (int nt = 0; nt < 8; nt++) {
            int r0 = cta_m + m_base + mt * 16 + g;
            int c0 = cta_n + n_base + nt * 8 + 2 * t;
            float b0 = bias[c0], b1 = bias[c0 + 1];
            float v00 = acc[mt][nt][0] + b0, v01 = acc[mt][nt][1] + b1;
            float v10 = acc[mt][nt][2] + b0, v11 = acc[mt][nt][3] + b1;
            if (round_out) {
                v00 = __uint_as_float(f2tf32(v00));
                v01 = __uint_as_float(f2tf32(v01));
                v10 = __uint_as_float(f2tf32(v10));
                v11 = __uint_as_float(f2tf32(v11));
            }
            *(float2*)(C + (size_t)r0 * D_MODEL + c0)       = make_float2(v00, v01);
            *(float2*)(C + (size_t)(r0 + 8) * D_MODEL + c0) = make_float2(v10, v11);
        }
    }
}

// ---------------------------------------------------------------------------
// Flash attention — byte-identical to round 9 (packed f32x2 exp2 softmax,
// rescale-skip vote, LDS.128 K/V fragments, sigma-packed V, plain epilogue).
// ---------------------------------------------------------------------------
#define QTILE 128
#define KSTG 5120
#define VSTG 5152
#define ATTN_SMEM ((2 * KSTG + 2 * VSTG) * 4)   // 82176 B

__global__ void __launch_bounds__(256, 2)
attn_kernel()
{
    extern __shared__ float sm[];
    float* Ks = sm;
    float* Vs = sm + 2 * KSTG;
    const uint32_t sK = smem_u32(Ks);
    const uint32_t sV = smem_u32(Vs);

    const int tid  = threadIdx.x;
    const int warp = tid >> 5, lane = tid & 31;
    const int g = lane >> 2, t = lane & 3;
    const int b = blockIdx.z, h = blockIdx.y;
    const int s0 = blockIdx.x * QTILE;
    const int q0 = warp * 16;

    {
        const float* Qg = g_Q + ((size_t)(b * N_SEQ + s0)) * D_MODEL + h * D_HEAD;
        #pragma unroll
        for (int i = 0; i < 8; i++) {
            int idx = tid + i * 256;
            int r = idx >> 4, c = idx & 15;
            cp16(sK + r * 272 + c * 16, Qg + (size_t)r * D_MODEL + c * 4);
        }
        cp_commit(); cp_wait0();
        __syncthreads();
    }
    uint32_t qf[8][4];
    #pragma unroll
    for (int kk = 0; kk < 8; kk++) {
        const int k0 = kk * 8;
        qf[kk][0] = __float_as_uint(Ks[(q0 + g)     * 68 + k0 + t]     * 0.125f);
        qf[kk][1] = __float_as_uint(Ks[(q0 + g + 8) * 68 + k0 + t]     * 0.125f);
        qf[kk][2] = __float_as_uint(Ks[(q0 + g)     * 68 + k0 + t + 4] * 0.125f);
        qf[kk][3] = __float_as_uint(Ks[(q0 + g + 8) * 68 + k0 + t + 4] * 0.125f);
    }
    __syncthreads();

    auto issue_kv = [&](int kt, int buf) {
        const float* Kg = g_Kp + ((size_t)(b * N_SEQ + kt * 64)) * D_MODEL + h * D_HEAD;
        const float* Vg = g_Vp + ((size_t)(((b * 32 + kt) << 4) + h)) * 4096;
        #pragma unroll
        for (int i = 0; i < 4; i++) {
            int idx = tid + i * 256;
            int r = idx >> 4, tt = (idx >> 2) & 3, c = idx & 3;
            cp16(sK + buf * 20480 + r * 320 + tt * 80 + c * 16,
                 Kg + (size_t)r * D_MODEL + tt * 16 + c * 4);
        }
        #pragma unroll
        for (int i = 0; i < 4; i++) {
            int idx = tid + i * 256;
            int tt = idx >> 8, n = (idx >> 2) & 63, c = idx & 3;
            cp16(sV + buf * 20608 + tt * 5152 + n * 80 + c * 16,
                 Vg + tt * 1024 + n * 16 + c * 4);
        }
        cp_commit();
    };

    float m0 = -1e30f, m1 = -1e30f, l0 = 0.f, l1 = 0.f;
    float o[8][4];
    #pragma unroll
    for (int dt = 0; dt < 8; dt++)
        #pragma unroll
        for (int e = 0; e < 4; e++) o[dt][e] = 0.f;

    issue_kv(0, 0);

    const int NT = N_SEQ / 64;
    for (int kt = 0; kt < NT; kt++) {
        cp_wait0();
        __syncthreads();
        if (kt + 1 < NT) issue_kv(kt + 1, (kt + 1) & 1);

        const float* Kb = Ks + (kt & 1) * KSTG;
        const float* Vb = Vs + (kt & 1) * VSTG;

        float s[8][4];
        #pragma unroll
        for (int nt = 0; nt < 8; nt++) {
            s[nt][0] = s[nt][1] = s[nt][2] = s[nt][3] = 0.f;
            const float4* kr = (const float4*)(Kb + (nt * 8 + g) * 80 + t * 20);
            float4 x0 = kr[0], x1 = kr[1], x2 = kr[2], x3 = kr[3];
            uint32_t kf[16] = {
                __float_as_uint(x0.x), __float_as_uint(x0.y),
                __float_as_uint(x0.z), __float_as_uint(x0.w),
                __float_as_uint(x1.x), __float_as_uint(x1.y),
                __float_as_uint(x1.z), __float_as_uint(x1.w),
                __float_as_uint(x2.x), __float_as_uint(x2.y),
                __float_as_uint(x2.z), __float_as_uint(x2.w),
                __float_as_uint(x3.x), __float_as_uint(x3.y),
                __float_as_uint(x3.z), __float_as_uint(x3.w)};
            #pragma unroll
            for (int ss = 0; ss < 8; ss++) {
                uint32_t b2[2] = {kf[2 * ss], kf[2 * ss + 1]};
                mma_tf32(s[nt], qf[ss], b2);
            }
        }

        float tm0 = -1e30f, tm1 = -1e30f;
        #pragma unroll
        for (int nt = 0; nt < 8; nt++) {
            tm0 = fmaxf(tm0, fmaxf(s[nt][0], s[nt][1]));
            tm1 = fmaxf(tm1, fmaxf(s[nt][2], s[nt][3]));
        }
        tm0 = fmaxf(tm0, __shfl_xor_sync(0xffffffffu, tm0, 1));
        tm0 = fmaxf(tm0, __shfl_xor_sync(0xffffffffu, tm0, 2));
        tm1 = fmaxf(tm1, __shfl_xor_sync(0xffffffffu, tm1, 1));
        tm1 = fmaxf(tm1, __shfl_xor_sync(0xffffffffu, tm1, 2));

        const float nm0 = fmaxf(m0, tm0), nm1 = fmaxf(m1, tm1);
        const bool changed = (nm0 != m0) || (nm1 != m1);

        const float L2E = 1.4426950408889634f;
        const uint64_t L2E2  = pk2(L2E, L2E);
        const uint64_t NM0_2 = pk2(-nm0 * L2E, -nm0 * L2E);
        const uint64_t NM1_2 = pk2(-nm1 * L2E, -nm1 * L2E);
        const uint64_t MAG2  = pk2(12582912.0f, 12582912.0f);
        const uint64_t NMAG2 = pk2(-12582912.0f, -12582912.0f);
        const uint64_t NEG1  = pk2(-1.0f, -1.0f);
        const uint64_t PC0   = pk2(1.0f, 1.0f);
        const uint64_t PC1   = pk2(0.6931471805599453f, 0.6931471805599453f);
        const uint64_t PC2   = pk2(0.2402265069591007f, 0.2402265069591007f);
        const uint64_t PC3   = pk2(0.0555041086648216f, 0.0555041086648216f);
        const uint64_t PC4   = pk2(0.0096181291076285f, 0.0096181291076285f);

        auto exp2p = [&](uint64_t t2) -> uint64_t {
            uint64_t z2  = padd2(t2, MAG2);
            uint64_t km2 = padd2(z2, NMAG2);
            uint64_t f2  = pfma2(km2, NEG1, t2);
            uint64_t r   = pfma2(PC4, f2, PC3);
            r = pfma2(r, f2, PC2);
            r = pfma2(r, f2, PC1);
            r = pfma2(r, f2, PC0);
            uint32_t zl, zh;
            upk2u(z2, zl, zh);
            uint32_t sl = (zl << 23) + 0x3F800000u;
            uint32_t sh = (zh << 23) + 0x3F800000u;
            return pmul2(r, pk2u(sl, sh));
        };

        uint64_t rsA = pk2(0.f, 0.f), rsB = pk2(0.f, 0.f);
        #pragma unroll
        for (int nt = 0; nt < 8; nt++) {
            uint64_t d0 = pk2(s[nt][0], s[nt][1]);
            uint64_t d1 = pk2(s[nt][2], s[nt][3]);
            uint64_t p0 = exp2p(pfma2(d0, L2E2, NM0_2));
            uint64_t p1 = exp2p(pfma2(d1, L2E2, NM1_2));
            rsA = padd2(rsA, p0);
            rsB = padd2(rsB, p1);
            float a0, a1;
            upk2(p0, a0, a1);
            s[nt][0] = __uint_as_float(f2tf32(a0));
            s[nt][1] = __uint_as_float(f2tf32(a1));
            upk2(p1, a0, a1);
            s[nt][2] = __uint_as_float(f2tf32(a0));
            s[nt][3] = __uint_as_float(f2tf32(a1));
        }
        float ra, rb;
        upk2(rsA, ra, rb);
        float rs0 = ra + rb;
        upk2(rsB, ra, rb);
        float rs1 = ra + rb;
        rs0 += __shfl_xor_sync(0xffffffffu, rs0, 1);
        rs0 += __shfl_xor_sync(0xffffffffu, rs0, 2);
        rs1 += __shfl_xor_sync(0xffffffffu, rs1, 1);
        rs1 += __shfl_xor_sync(0xffffffffu, rs1, 2);

        if (__any_sync(0xffffffffu, changed)) {
            const float c0 = fast_exp(m0 - nm0), c1 = fast_exp(m1 - nm1);
            l0 = l0 * c0 + rs0;
            l1 = l1 * c1 + rs1;
            #pragma unroll
            for (int dt = 0; dt < 8; dt++) {
                o[dt][0] *= c0; o[dt][1] *= c0;
                o[dt][2] *= c1; o[dt][3] *= c1;
            }
        } else {
            l0 += rs0;
            l1 += rs1;
        }
        m0 = nm0; m1 = nm1;

        #pragma unroll
        for (int dt = 0; dt < 8; dt++) {
            const float4* vr = (const float4*)(Vb + t * 1288 + (dt * 8 + g) * 20);
            float4 y0 = vr[0], y1 = vr[1], y2 = vr[2], y3 = vr[3];
            uint32_t vf[16] = {
                __float_as_uint(y0.x), __float_as_uint(y0.y),
                __float_as_uint(y0.z), __float_as_uint(y0.w),
                __float_as_uint(y1.x), __float_as_uint(y1.y),
                __float_as_uint(y1.z), __float_as_uint(y1.w),
                __float_as_uint(y2.x), __float_as_uint(y2.y),
                __float_as_uint(y2.z), __float_as_uint(y2.w),
                __float_as_uint(y3.x), __float_as_uint(y3.y),
                __float_as_uint(y3.z), __float_as_uint(y3.w)};
            #pragma unroll
            for (int kk = 0; kk < 8; kk++) {
                uint32_t a4[4] = {__float_as_uint(s[kk][0]), __float_as_uint(s[kk][2]),
                                  __float_as_uint(s[kk][1]), __float_as_uint(s[kk][3])};
                uint32_t b2[2] = {vf[2 * kk], vf[2 * kk + 1]};
                mma_tf32(o[dt], a4, b2);
            }
        }
    }

    const float inv0 = 1.0f / l0, inv1 = 1.0f / l1;
    float* Cg = g_CTX + ((size_t)(b * N_SEQ + s0 + q0)) * D_MODEL + h * D_HEAD;
    #pragma unroll
    for (int dt = 0; dt < 8; dt++) {
        const int cc = dt * 8 + 2 * t;
        *(float2*)(Cg + (size_t)g * D_MODEL + cc) = make_float2(
            __uint_as_float(f2tf32(o[dt][0] * inv0)),
            __uint_as_float(f2tf32(o[dt][1] * inv0)));
        *(float2*)(Cg + (size_t)(g + 8) * D_MODEL + cc) = make_float2(
            __uint_as_float(f2tf32(o[dt][2] * inv1)),
            __uint_as_float(f2tf32(o[dt][3] * inv1)));
    }
}

// ---------------------------------------------------------------------------
extern "C" void kernel_launch(void* const* d_in, const int* in_sizes, int n_in,
                              void* d_out, int out_size)
{
    (void)in_sizes; (void)n_in; (void)out_size;
    const float* q  = (const float*)d_in[0];
    const float* k  = (const float*)d_in[1];
    const float* v  = (const float*)d_in[2];
    const float* Wq = (const float*)d_in[3];
    const float* bq = (const float*)d_in[4];
    const float* Wk = (const float*)d_in[5];
    const float* bk = (const float*)d_in[6];
    const float* Wv = (const float*)d_in[7];
    const float* bv = (const float*)d_in[8];
    const float* Wo = (const float*)d_in[9];
    const float* bo = (const float*)d_in[10];
    float* out = (float*)d_out;

    float *Qd, *K0, *V0, *Kp, *Vp, *Cd, *qc, *kc, *vc, *Wqp, *Wkp, *Wvp, *Wop;
    cudaGetSymbolAddress((void**)&Qd,  g_Q);
    cudaGetSymbolAddress((void**)&K0,  g_K0);
    cudaGetSymbolAddress((void**)&V0,  g_V0);
    cudaGetSymbolAddress((void**)&Kp,  g_Kp);
    cudaGetSymbolAddress((void**)&Vp,  g_Vp);
    cudaGetSymbolAddress((void**)&Cd,  g_CTX);
    cudaGetSymbolAddress((void**)&qc,  g_qc);
    cudaGetSymbolAddress((void**)&kc,  g_kc);
    cudaGetSymbolAddress((void**)&vc,  g_vc);
    cudaGetSymbolAddress((void**)&Wqp, g_Wqp);
    cudaGetSymbolAddress((void**)&Wkp, g_Wkp);
    cudaGetSymbolAddress((void**)&Wvp, g_Wvp);
    cudaGetSymbolAddress((void**)&Wop, g_Wop);

    cudaFuncSetAttribute(gemm_bias_kernel,
                         cudaFuncAttributeMaxDynamicSharedMemorySize, GEMM_SMEM);
    cudaFuncSetAttribute(attn_kernel,
                         cudaFuncAttributeMaxDynamicSharedMemorySize, ATTN_SMEM);

    const int N4_IN = N_ROWS * D_MODEL / 4;
    // Launch order puts attn 6th so ncu (-s 5 -c 1) captures it.
    cvt_in_kernel<<<dim3(592, 1, 3), 256>>>(             // #1
        (const float4*)q, (float4*)qc, (const float4*)k, (float4*)kc,
        (const float4*)v, (float4*)vc, N4_IN);
    cvt_wp_kernel<<<dim3(32, 32, 4), 256>>>(             // #2
        Wq, Wqp, Wk, Wkp, Wv, Wvp, Wo, Wop);

    GemmSet sq{qc, Wqp, bq, Qd};
    GemmSet sk{kc, Wkp, bk, K0};
    GemmSet sv{vc, Wvp, bv, V0};
    gemm_bias_kernel<<<dim3(D_MODEL / BN, N_ROWS / BM, 3), 256, GEMM_SMEM>>>(
        sq, sk, sv, 1);                                  // #3

    pack_k_kernel<<<2368, 256>>>(K0, Kp);                // #4
    pack_v_kernel<<<dim3(N_ROWS / 64, N_HEADS), 256>>>(V0, Vp);   // #5

    attn_kernel<<<dim3(N_SEQ / QTILE, N_HEADS, N_BATCH), 256, ATTN_SMEM>>>();  // #6

    GemmSet so{Cd, Wop, bo, out};
    gemm_bias_kernel<<<dim3(D_MODEL / BN, N_ROWS / BM, 1), 256, GEMM_SMEM>>>(
        so, so, so, 0);                                  // #7
}

// round 11
// speedup vs baseline: 1.0723x; 1.0723x over previous
#include <cuda_runtime.h>
#include <cstdint>
#include <cstddef>

#define D_MODEL 1024
#define N_BATCH 4
#define N_SEQ   2048
#define N_HEADS 16
#define D_HEAD  64
#define N_ROWS  (N_BATCH * N_SEQ)   // 8192

// Scratch (device-global: no allocations allowed in kernel_launch).
__device__ float g_Q  [(size_t)N_ROWS * D_MODEL];  // plain, tf32-rounded
__device__ float g_K0 [(size_t)N_ROWS * D_MODEL];  // plain K, tf32-rounded
__device__ float g_V0 [(size_t)N_ROWS * D_MODEL];  // plain V, tf32-rounded
__device__ float g_Kp [(size_t)N_ROWS * D_MODEL];  // packed K per head chunk
__device__ float g_Vp [(size_t)N_ROWS * D_MODEL];  // packed V per (tile,h) block
__device__ float g_CTX[(size_t)N_ROWS * D_MODEL];  // plain, tf32-rounded
// tf32-pre-rounded plain copies of inputs
__device__ float g_qc[(size_t)N_ROWS * D_MODEL];
__device__ float g_kc[(size_t)N_ROWS * D_MODEL];
__device__ float g_vc[(size_t)N_ROWS * D_MODEL];
// weights: tf32-rounded, B-frag packed: Wp[n][kt:32][t:4][j:8] = W[kt*32+t+4j][n]
__device__ float g_Wqp[(size_t)D_MODEL * D_MODEL];
__device__ float g_Wkp[(size_t)D_MODEL * D_MODEL];
__device__ float g_Wvp[(size_t)D_MODEL * D_MODEL];
__device__ float g_Wop[(size_t)D_MODEL * D_MODEL];

// ---------------------------------------------------------------------------
// Helpers
// ---------------------------------------------------------------------------
__device__ __forceinline__ uint32_t f2tf32(float x) {
    uint32_t r;
    asm("cvt.rna.tf32.f32 %0, %1;" : "=r"(r) : "f"(x));
    return r;
}
__device__ __forceinline__ void mma_tf32(float d[4], const uint32_t a[4], const uint32_t b[2]) {
    asm volatile(
        "mma.sync.aligned.m16n8k8.row.col.f32.tf32.tf32.f32 "
        "{%0,%1,%2,%3}, {%4,%5,%6,%7}, {%8,%9}, {%0,%1,%2,%3};\n"
        : "+f"(d[0]), "+f"(d[1]), "+f"(d[2]), "+f"(d[3])
        : "r"(a[0]), "r"(a[1]), "r"(a[2]), "r"(a[3]), "r"(b[0]), "r"(b[1]));
}
__device__ __forceinline__ void cp16(uint32_t s, const void* g) {
    asm volatile("cp.async.cg.shared.global [%0], [%1], 16;\n" :: "r"(s), "l"(g));
}
__device__ __forceinline__ void cp_commit() { asm volatile("cp.async.commit_group;\n"); }
__device__ __forceinline__ void cp_wait0()  { asm volatile("cp.async.wait_group 0;\n"); }
__device__ __forceinline__ uint32_t smem_u32(const void* p) {
    uint32_t a;
    asm("{ .reg .u64 t; cvta.to.shared.u64 t, %1; cvt.u32.u64 %0, t; }"
        : "=r"(a) : "l"(p));
    return a;
}

// ---- packed f32x2 (Blackwell FFMA2 pipe) ----
__device__ __forceinline__ uint64_t pk2(float a, float b) {
    uint64_t r; asm("mov.b64 %0, {%1, %2};" : "=l"(r) : "f"(a), "f"(b)); return r;
}
__device__ __forceinline__ void upk2(uint64_t v, float& a, float& b) {
    asm("mov.b64 {%0, %1}, %2;" : "=f"(a), "=f"(b) : "l"(v));
}
__device__ __forceinline__ void upk2u(uint64_t v, uint32_t& a, uint32_t& b) {
    asm("mov.b64 {%0, %1}, %2;" : "=r"(a), "=r"(b) : "l"(v));
}
__device__ __forceinline__ uint64_t pk2u(uint32_t a, uint32_t b) {
    uint64_t r; asm("mov.b64 %0, {%1, %2};" : "=l"(r) : "r"(a), "r"(b)); return r;
}
__device__ __forceinline__ uint64_t pfma2(uint64_t a, uint64_t b, uint64_t c) {
    uint64_t r;
    asm("fma.rn.f32x2 %0, %1, %2, %3;" : "=l"(r) : "l"(a), "l"(b), "l"(c));
    return r;
}
__device__ __forceinline__ uint64_t padd2(uint64_t a, uint64_t b) {
    uint64_t r; asm("add.rn.f32x2 %0, %1, %2;" : "=l"(r) : "l"(a), "l"(b)); return r;
}
__device__ __forceinline__ uint64_t pmul2(uint64_t a, uint64_t b) {
    uint64_t r; asm("mul.rn.f32x2 %0, %1, %2;" : "=l"(r) : "l"(a), "l"(b)); return r;
}

// scalar exp(x) for x <= 0 with clamp (correction factors only). ~3e-6 rel.
__device__ __forceinline__ float fast_exp(float x) {
    float t = fmaxf(x * 1.4426950408889634f, -126.0f);
    float z = t + 12582912.0f;
    int  ki = __float_as_int(z) - 0x4B400000;
    float f = t - (z - 12582912.0f);
    float u = f * 0.6931471805599453f;
    float p = 1.0f + u * (1.0f + u * (0.5f + u * (0.16666667f +
              u * (0.041666668f + u * 0.008333334f))));
    return __int_as_float(__float_as_int(p) + (ki << 23));
}

// ---------------------------------------------------------------------------
// Fused prep (ONE launch): z = 0..2 input tf32 pre-round (q,k,v);
// z = 3..6 weight transform+pack (Wq,Wk,Wv,Wo).
// Wp[n][kt*32 + t*8 + j] = round_tf32(W[kt*32 + t + 4*j][n]).
// ---------------------------------------------------------------------------
__global__ void __launch_bounds__(256)
prep_kernel(const float4* q,  float4* qc,  const float4* k,  float4* kc,
            const float4* v,  float4* vc,
            const float* Wq, float* Wqp, const float* Wk, float* Wkp,
            const float* Wv, float* Wvp, const float* Wo, float* Wop)
{
    __shared__ float tle[32][33];
    const int z = blockIdx.z;
    if (z < 3) {
        const float4* __restrict__ in  = (z == 0) ? q : (z == 1) ? k : v;
        float4* __restrict__ out       = (z == 0) ? qc : (z == 1) ? kc : vc;
        const int n4 = N_ROWS * D_MODEL / 4;
        for (int i = blockIdx.x * blockDim.x + threadIdx.x; i < n4;
             i += gridDim.x * blockDim.x) {
            float4 w = in[i];
            w.x = __uint_as_float(f2tf32(w.x));
            w.y = __uint_as_float(f2tf32(w.y));
            w.z = __uint_as_float(f2tf32(w.z));
            w.w = __uint_as_float(f2tf32(w.w));
            out[i] = w;
        }
    } else {
        const float* __restrict__ W = (z == 3) ? Wq : (z == 4) ? Wk
                                    : (z == 5) ? Wv : Wo;
        float* __restrict__ P       = (z == 3) ? Wqp : (z == 4) ? Wkp
                                    : (z == 5) ? Wvp : Wop;
        const int tile = blockIdx.x;          // 1024 tiles of 32x32
        const int n0 = (tile & 31) * 32, k0 = (tile >> 5) * 32;
        const int tx = threadIdx.x & 31, ty = threadIdx.x >> 5;   // 32 x 8
        #pragma unroll
        for (int j = 0; j < 32; j += 8)
            tle[ty + j][tx] = W[(size_t)(k0 + ty + j) * D_MODEL + n0 + tx];
        __syncthreads();
        #pragma unroll
        for (int j = 0; j < 32; j += 8) {
            const int r = ty + j;             // output n-row within tile
            const int p = tx;                 // packed position 0..31
            const int ksrc = (p >> 3) + 4 * (p & 7);   // t + 4*j
            P[(size_t)(n0 + r) * D_MODEL + k0 + p] =
                __uint_as_float(f2tf32(tle[ksrc][r]));
        }
    }
}

// ---------------------------------------------------------------------------
// Fused K+V pack (ONE launch): z=0 K pack (grid-stride), z=1 V pack per
// (tile,h). Mappings identical to rounds 8-10 (bit-verified).
// ---------------------------------------------------------------------------
__global__ void __launch_bounds__(256)
pack_kv_kernel(const float* __restrict__ K0, float* __restrict__ Kp,
               const float* __restrict__ V0, float* __restrict__ Vp)
{
    __shared__ float sm[64][65];
    if (blockIdx.z == 0) {
        // K pack: out[p] = in[(p%16)*4 + p/16] within each 64-float chunk
        const int flat = blockIdx.y * gridDim.x + blockIdx.x;
        const int nthr = gridDim.x * gridDim.y * 256;
        const int total2 = N_ROWS * D_MODEL / 2;
        for (int i = flat * 256 + threadIdx.x; i < total2; i += nthr) {
            const int o = i * 2, chunk = o >> 6, p = o & 63;   // p even
            const int dh = ((p & 15) << 2) + (p >> 4);
            const float* base = K0 + (size_t)chunk * 64;
            *(float2*)(Kp + (size_t)chunk * 64 + p) =
                make_float2(base[dh], base[dh + 4]);
        }
    } else {
        // V pack per (tile, h), smem-staged, coalesced both sides
        const int tile = blockIdx.x, h = blockIdx.y;
        const int tid = threadIdx.x;
        const float* src = V0 + (size_t)tile * 64 * D_MODEL + h * 64;
        #pragma unroll
        for (int i = 0; i < 4; i++) {
            const int idx = tid + i * 256;
            const int rl = idx >> 4, c4 = (idx & 15) * 4;
            float4 w = *(const float4*)(src + (size_t)rl * D_MODEL + c4);
            sm[rl][c4] = w.x; sm[rl][c4 + 1] = w.y;
            sm[rl][c4 + 2] = w.z; sm[rl][c4 + 3] = w.w;
        }
        __syncthreads();
        float* dst = Vp + (size_t)(tile * 16 + h) * 4096;
        #pragma unroll
        for (int i = 0; i < 4; i++) {
            const int o = (tid + i * 256) * 4;
            float4 w;
            #pragma unroll
            for (int e = 0; e < 4; e++) {
                const int oo = o + e;
                const int tt = oo >> 10, dh = (oo >> 4) & 63, lo = oo & 15;
                const int rl = ((lo >> 1) << 3) + (tt << 1) + (lo & 1);
                ((float*)&w)[e] = sm[rl][dh];
            }
            *(float4*)(dst + o) = w;
        }
    }
}

// ---------------------------------------------------------------------------
// GEMM: C[8192,1024] = A @ W + bias. A plain tf32; W B-frag packed.
// __launch_bounds__(256, 2) FORCES regs<=128 so 2 CTAs/SM survive the
// hoisted A fragments (round-10 regression = occupancy halving).
// Accumulation order identical to round 3.
// ---------------------------------------------------------------------------
#define BM 128
#define BN 128
#define BK 32
#define ASTR 36
#define BSTR2 36
#define A_BUF (BM * ASTR)      // 4608 floats
#define B_BUF (BN * BSTR2)     // 4608 floats
#define GEMM_SMEM ((2 * A_BUF + 2 * B_BUF) * 4)   // 73728 B

struct GemmSet { const float* A; const float* Wp; const float* bias; float* C; };

__global__ void __launch_bounds__(256, 2)
gemm_bias_kernel(GemmSet s0, GemmSet s1, GemmSet s2, int round_out)
{
    const GemmSet& S = (blockIdx.z == 0) ? s0 : (blockIdx.z == 1) ? s1 : s2;
    const float* __restrict__ A    = S.A;
    const float* __restrict__ Wp   = S.Wp;
    const float* __restrict__ bias = S.bias;
    float* __restrict__ C          = S.C;

    extern __shared__ float smem[];
    float* As = smem;                       // [2][128][36]
    float* Bs = smem + 2 * A_BUF;           // [2][128][36]
    const uint32_t sA = smem_u32(As);
    const uint32_t sB = smem_u32(Bs);

    const int tid  = threadIdx.x;
    const int warp = tid >> 5, lane = tid & 31;
    const int g = lane >> 2, t = lane & 3;
    const int wm = warp >> 1, wn = warp & 1;
    const int m_base = wm * 32, n_base = wn * 64;
    const int cta_m = blockIdx.y * BM;
    const int cta_n = blockIdx.x * BN;

    float acc[2][8][4];
    #pragma unroll
    for (int i = 0; i < 2; i++)
        #pragma unroll
        for (int j = 0; j < 8; j++)
            #pragma unroll
            for (int e = 0; e < 4; e++) acc[i][j][e] = 0.f;

    auto issue_loads = [&](int kt, int buf) {
        const float* Ag = A + (size_t)cta_m * D_MODEL + kt * BK;
        #pragma unroll
        for (int i = 0; i < 4; i++) {           // A: 128 rows x 8 chunks
            int idx = tid + i * 256;
            int r = idx >> 3, c = (idx & 7) * 4;
            cp16(sA + (uint32_t)(buf * A_BUF + r * ASTR + c) * 4,
                 Ag + (size_t)r * D_MODEL + c);
        }
        const float* Bg = Wp + (size_t)cta_n * D_MODEL + kt * BK;
        #pragma unroll
        for (int i = 0; i < 4; i++) {           // B: 128 n-rows x 8 chunks
            int idx = tid + i * 256;
            int r = idx >> 3, c = (idx & 7) * 4;
            cp16(sB + (uint32_t)(buf * B_BUF + r * BSTR2 + c) * 4,
                 Bg + (size_t)r * D_MODEL + c);
        }
        cp_commit();
    };

    issue_loads(0, 0);

    const int KT = D_MODEL / BK;  // 32
    for (int kt = 0; kt < KT; kt++) {
        cp_wait0();
        __syncthreads();
        if (kt + 1 < KT) issue_loads(kt + 1, (kt + 1) & 1);

        const float* Ab = As + (kt & 1) * A_BUF;
        const float* Bb = Bs + (kt & 1) * B_BUF;

        uint32_t af[4][2][4];   // [kk][mt][4]
        #pragma unroll
        for (int kk = 0; kk < 4; kk++) {
            const int k0 = kk * 8;
            #pragma unroll
            for (int mt = 0; mt < 2; mt++) {
                const int m0 = m_base + mt * 16;
                af[kk][mt][0] = __float_as_uint(Ab[(m0 + g)     * ASTR + k0 + t]);
                af[kk][mt][1] = __float_as_uint(Ab[(m0 + g + 8) * ASTR + k0 + t]);
                af[kk][mt][2] = __float_as_uint(Ab[(m0 + g)     * ASTR + k0 + t + 4]);
                af[kk][mt][3] = __float_as_uint(Ab[(m0 + g + 8) * ASTR + k0 + t + 4]);
            }
        }
        #pragma unroll
        for (int nt = 0; nt < 8; nt++) {
            const float4* bp = (const float4*)
                (Bb + (n_base + nt * 8 + g) * BSTR2 + t * 8);
            float4 y0 = bp[0], y1 = bp[1];
            const uint32_t pw[8] = {
                __float_as_uint(y0.x), __float_as_uint(y0.y),
                __float_as_uint(y0.z), __float_as_uint(y0.w),
                __float_as_uint(y1.x), __float_as_uint(y1.y),
                __float_as_uint(y1.z), __float_as_uint(y1.w)};
            #pragma unroll
            for (int kk = 0; kk < 4; kk++) {
                uint32_t b2[2] = {pw[2 * kk], pw[2 * kk + 1]};
                mma_tf32(acc[0][nt], af[kk][0], b2);
                mma_tf32(acc[1][nt], af[kk][1], b2);
            }
        }
    }

    #pragma unroll
    for (int mt = 0; mt < 2; mt++) {
        #pragma unroll
        for (int nt = 0; nt < 8; nt++) {
            int r0 = cta_m + m_base + mt * 16 + g;
            int c0 = cta_n + n_base + nt * 8 + 2 * t;
            float b0 = bias[c0], b1 = bias[c0 + 1];
            float v00 = acc[mt][nt][0] + b0, v01 = acc[mt][nt][1] + b1;
            float v10 = acc[mt][nt][2] + b0, v11 = acc[mt][nt][3] + b1;
            if (round_out) {
                v00 = __uint_as_float(f2tf32(v00));
                v01 = __uint_as_float(f2tf32(v01));
                v10 = __uint_as_float(f2tf32(v10));
                v11 = __uint_as_float(f2tf32(v11));
            }
            *(float2*)(C + (size_t)r0 * D_MODEL + c0)       = make_float2(v00, v01);
            *(float2*)(C + (size_t)(r0 + 8) * D_MODEL + c0) = make_float2(v10, v11);
        }
    }
}

// ---------------------------------------------------------------------------
// Flash attention — byte-identical to rounds 9/10.
// ---------------------------------------------------------------------------
#define QTILE 128
#define KSTG 5120
#define VSTG 5152
#define ATTN_SMEM ((2 * KSTG + 2 * VSTG) * 4)   // 82176 B

__global__ void __launch_bounds__(256, 2)
attn_kernel()
{
    extern __shared__ float sm[];
    float* Ks = sm;
    float* Vs = sm + 2 * KSTG;
    const uint32_t sK = smem_u32(Ks);
    const uint32_t sV = smem_u32(Vs);

    const int tid  = threadIdx.x;
    const int warp = tid >> 5, lane = tid & 31;
    const int g = lane >> 2, t = lane & 3;
    const int b = blockIdx.z, h = blockIdx.y;
    const int s0 = blockIdx.x * QTILE;
    const int q0 = warp * 16;

    {
        const float* Qg = g_Q + ((size_t)(b * N_SEQ + s0)) * D_MODEL + h * D_HEAD;
        #pragma unroll
        for (int i = 0; i < 8; i++) {
            int idx = tid + i * 256;
            int r = idx >> 4, c = idx & 15;
            cp16(sK + r * 272 + c * 16, Qg + (size_t)r * D_MODEL + c * 4);
        }
        cp_commit(); cp_wait0();
        __syncthreads();
    }
    uint32_t qf[8][4];
    #pragma unroll
    for (int kk = 0; kk < 8; kk++) {
        const int k0 = kk * 8;
        qf[kk][0] = __float_as_uint(Ks[(q0 + g)     * 68 + k0 + t]     * 0.125f);
        qf[kk][1] = __float_as_uint(Ks[(q0 + g + 8) * 68 + k0 + t]     * 0.125f);
        qf[kk][2] = __float_as_uint(Ks[(q0 + g)     * 68 + k0 + t + 4] * 0.125f);
        qf[kk][3] = __float_as_uint(Ks[(q0 + g + 8) * 68 + k0 + t + 4] * 0.125f);
    }
    __syncthreads();

    auto issue_kv = [&](int kt, int buf) {
        const float* Kg = g_Kp + ((size_t)(b * N_SEQ + kt * 64)) * D_MODEL + h * D_HEAD;
        const float* Vg = g_Vp + ((size_t)(((b * 32 + kt) << 4) + h)) * 4096;
        #pragma unroll
        for (int i = 0; i < 4; i++) {
            int idx = tid + i * 256;
            int r = idx >> 4, tt = (idx >> 2) & 3, c = idx & 3;
            cp16(sK + buf * 20480 + r * 320 + tt * 80 + c * 16,
                 Kg + (size_t)r * D_MODEL + tt * 16 + c * 4);
        }
        #pragma unroll
        for (int i = 0; i < 4; i++) {
            int idx = tid + i * 256;
            int tt = idx >> 8, n = (idx >> 2) & 63, c = idx & 3;
            cp16(sV + buf * 20608 + tt * 5152 + n * 80 + c * 16,
                 Vg + tt * 1024 + n * 16 + c * 4);
        }
        cp_commit();
    };

    float m0 = -1e30f, m1 = -1e30f, l0 = 0.f, l1 = 0.f;
    float o[8][4];
    #pragma unroll
    for (int dt = 0; dt < 8; dt++)
        #pragma unroll
        for (int e = 0; e < 4; e++) o[dt][e] = 0.f;

    issue_kv(0, 0);

    const int NT = N_SEQ / 64;
    for (int kt = 0; kt < NT; kt++) {
        cp_wait0();
        __syncthreads();
        if (kt + 1 < NT) issue_kv(kt + 1, (kt + 1) & 1);

        const float* Kb = Ks + (kt & 1) * KSTG;
        const float* Vb = Vs + (kt & 1) * VSTG;

        float s[8][4];
        #pragma unroll
        for (int nt = 0; nt < 8; nt++) {
            s[nt][0] = s[nt][1] = s[nt][2] = s[nt][3] = 0.f;
            const float4* kr = (const float4*)(Kb + (nt * 8 + g) * 80 + t * 20);
            float4 x0 = kr[0], x1 = kr[1], x2 = kr[2], x3 = kr[3];
            uint32_t kf[16] = {
                __float_as_uint(x0.x), __float_as_uint(x0.y),
                __float_as_uint(x0.z), __float_as_uint(x0.w),
                __float_as_uint(x1.x), __float_as_uint(x1.y),
                __float_as_uint(x1.z), __float_as_uint(x1.w),
                __float_as_uint(x2.x), __float_as_uint(x2.y),
                __float_as_uint(x2.z), __float_as_uint(x2.w),
                __float_as_uint(x3.x), __float_as_uint(x3.y),
                __float_as_uint(x3.z), __float_as_uint(x3.w)};
            #pragma unroll
            for (int ss = 0; ss < 8; ss++) {
                uint32_t b2[2] = {kf[2 * ss], kf[2 * ss + 1]};
                mma_tf32(s[nt], qf[ss], b2);
            }
        }

        float tm0 = -1e30f, tm1 = -1e30f;
        #pragma unroll
        for (int nt = 0; nt < 8; nt++) {
            tm0 = fmaxf(tm0, fmaxf(s[nt][0], s[nt][1]));
            tm1 = fmaxf(tm1, fmaxf(s[nt][2], s[nt][3]));
        }
        tm0 = fmaxf(tm0, __shfl_xor_sync(0xffffffffu, tm0, 1));
        tm0 = fmaxf(tm0, __shfl_xor_sync(0xffffffffu, tm0, 2));
        tm1 = fmaxf(tm1, __shfl_xor_sync(0xffffffffu, tm1, 1));
        tm1 = fmaxf(tm1, __shfl_xor_sync(0xffffffffu, tm1, 2));

        const float nm0 = fmaxf(m0, tm0), nm1 = fmaxf(m1, tm1);
        const bool changed = (nm0 != m0) || (nm1 != m1);

        const float L2E = 1.4426950408889634f;
        const uint64_t L2E2  = pk2(L2E, L2E);
        const uint64_t NM0_2 = pk2(-nm0 * L2E, -nm0 * L2E);
        const uint64_t NM1_2 = pk2(-nm1 * L2E, -nm1 * L2E);
        const uint64_t MAG2  = pk2(12582912.0f, 12582912.0f);
        const uint64_t NMAG2 = pk2(-12582912.0f, -12582912.0f);
        const uint64_t NEG1  = pk2(-1.0f, -1.0f);
        const uint64_t PC0   = pk2(1.0f, 1.0f);
        const uint64_t PC1   = pk2(0.6931471805599453f, 0.6931471805599453f);
        const uint64_t PC2   = pk2(0.2402265069591007f, 0.2402265069591007f);
        const uint64_t PC3   = pk2(0.0555041086648216f, 0.0555041086648216f);
        const uint64_t PC4   = pk2(0.0096181291076285f, 0.0096181291076285f);

        auto exp2p = [&](uint64_t t2) -> uint64_t {
            uint64_t z2  = padd2(t2, MAG2);
            uint64_t km2 = padd2(z2, NMAG2);
            uint64_t f2  = pfma2(km2, NEG1, t2);
            uint64_t r   = pfma2(PC4, f2, PC3);
            r = pfma2(r, f2, PC2);
            r = pfma2(r, f2, PC1);
            r = pfma2(r, f2, PC0);
            uint32_t zl, zh;
            upk2u(z2, zl, zh);
            uint32_t sl = (zl << 23) + 0x3F800000u;
            uint32_t sh = (zh << 23) + 0x3F800000u;
            return pmul2(r, pk2u(sl, sh));
        };

        uint64_t rsA = pk2(0.f, 0.f), rsB = pk2(0.f, 0.f);
        #pragma unroll
        for (int nt = 0; nt < 8; nt++) {
            uint64_t d0 = pk2(s[nt][0], s[nt][1]);
            uint64_t d1 = pk2(s[nt][2], s[nt][3]);
            uint64_t p0 = exp2p(pfma2(d0, L2E2, NM0_2));
            uint64_t p1 = exp2p(pfma2(d1, L2E2, NM1_2));
            rsA = padd2(rsA, p0);
            rsB = padd2(rsB, p1);
            float a0, a1;
            upk2(p0, a0, a1);
            s[nt][0] = __uint_as_float(f2tf32(a0));
            s[nt][1] = __uint_as_float(f2tf32(a1));
            upk2(p1, a0, a1);
            s[nt][2] = __uint_as_float(f2tf32(a0));
            s[nt][3] = __uint_as_float(f2tf32(a1));
        }
        float ra, rb;
        upk2(rsA, ra, rb);
        float rs0 = ra + rb;
        upk2(rsB, ra, rb);
        float rs1 = ra + rb;
        rs0 += __shfl_xor_sync(0xffffffffu, rs0, 1);
        rs0 += __shfl_xor_sync(0xffffffffu, rs0, 2);
        rs1 += __shfl_xor_sync(0xffffffffu, rs1, 1);
        rs1 += __shfl_xor_sync(0xffffffffu, rs1, 2);

        if (__any_sync(0xffffffffu, changed)) {
            const float c0 = fast_exp(m0 - nm0), c1 = fast_exp(m1 - nm1);
            l0 = l0 * c0 + rs0;
            l1 = l1 * c1 + rs1;
            #pragma unroll
            for (int dt = 0; dt < 8; dt++) {
                o[dt][0] *= c0; o[dt][1] *= c0;
                o[dt][2] *= c1; o[dt][3] *= c1;
            }
        } else {
            l0 += rs0;
            l1 += rs1;
        }
        m0 = nm0; m1 = nm1;

        #pragma unroll
        for (int dt = 0; dt < 8; dt++) {
            const float4* vr = (const float4*)(Vb + t * 1288 + (dt * 8 + g) * 20);
            float4 y0 = vr[0], y1 = vr[1], y2 = vr[2], y3 = vr[3];
            uint32_t vf[16] = {
                __float_as_uint(y0.x), __float_as_uint(y0.y),
                __float_as_uint(y0.z), __float_as_uint(y0.w),
                __float_as_uint(y1.x), __float_as_uint(y1.y),
                __float_as_uint(y1.z), __float_as_uint(y1.w),
                __float_as_uint(y2.x), __float_as_uint(y2.y),
                __float_as_uint(y2.z), __float_as_uint(y2.w),
                __float_as_uint(y3.x), __float_as_uint(y3.y),
                __float_as_uint(y3.z), __float_as_uint(y3.w)};
            #pragma unroll
            for (int kk = 0; kk < 8; kk++) {
                uint32_t a4[4] = {__float_as_uint(s[kk][0]), __float_as_uint(s[kk][2]),
                                  __float_as_uint(s[kk][1]), __float_as_uint(s[kk][3])};
                uint32_t b2[2] = {vf[2 * kk], vf[2 * kk + 1]};
                mma_tf32(o[dt], a4, b2);
            }
        }
    }

    const float inv0 = 1.0f / l0, inv1 = 1.0f / l1;
    float* Cg = g_CTX + ((size_t)(b * N_SEQ + s0 + q0)) * D_MODEL + h * D_HEAD;
    #pragma unroll
    for (int dt = 0; dt < 8; dt++) {
        const int cc = dt * 8 + 2 * t;
        *(float2*)(Cg + (size_t)g * D_MODEL + cc) = make_float2(
            __uint_as_float(f2tf32(o[dt][0] * inv0)),
            __uint_as_float(f2tf32(o[dt][1] * inv0)));
        *(float2*)(Cg + (size_t)(g + 8) * D_MODEL + cc) = make_float2(
            __uint_as_float(f2tf32(o[dt][2] * inv1)),
            __uint_as_float(f2tf32(o[dt][3] * inv1)));
    }
}

// ---------------------------------------------------------------------------
extern "C" void kernel_launch(void* const* d_in, const int* in_sizes, int n_in,
                              void* d_out, int out_size)
{
    (void)in_sizes; (void)n_in; (void)out_size;
    const float* q  = (const float*)d_in[0];
    const float* k  = (const float*)d_in[1];
    const float* v  = (const float*)d_in[2];
    const float* Wq = (const float*)d_in[3];
    const float* bq = (const float*)d_in[4];
    const float* Wk = (const float*)d_in[5];
    const float* bk = (const float*)d_in[6];
    const float* Wv = (const float*)d_in[7];
    const float* bv = (const float*)d_in[8];
    const float* Wo = (const float*)d_in[9];
    const float* bo = (const float*)d_in[10];
    float* out = (float*)d_out;

    float *Qd, *K0, *V0, *Kp, *Vp, *Cd, *qc, *kc, *vc, *Wqp, *Wkp, *Wvp, *Wop;
    cudaGetSymbolAddress((void**)&Qd,  g_Q);
    cudaGetSymbolAddress((void**)&K0,  g_K0);
    cudaGetSymbolAddress((void**)&V0,  g_V0);
    cudaGetSymbolAddress((void**)&Kp,  g_Kp);
    cudaGetSymbolAddress((void**)&Vp,  g_Vp);
    cudaGetSymbolAddress((void**)&Cd,  g_CTX);
    cudaGetSymbolAddress((void**)&qc,  g_qc);
    cudaGetSymbolAddress((void**)&kc,  g_kc);
    cudaGetSymbolAddress((void**)&vc,  g_vc);
    cudaGetSymbolAddress((void**)&Wqp, g_Wqp);
    cudaGetSymbolAddress((void**)&Wkp, g_Wkp);
    cudaGetSymbolAddress((void**)&Wvp, g_Wvp);
    cudaGetSymbolAddress((void**)&Wop, g_Wop);

    cudaFuncSetAttribute(gemm_bias_kernel,
                         cudaFuncAttributeMaxDynamicSharedMemorySize, GEMM_SMEM);
    cudaFuncSetAttribute(attn_kernel,
                         cudaFuncAttributeMaxDynamicSharedMemorySize, ATTN_SMEM);

    // Launch order calibrated so attn is my launch #4 (the slot ncu captured
    // in round 10).
    prep_kernel<<<dim3(1024, 1, 7), 256>>>(              // #1
        (const float4*)q, (float4*)qc, (const float4*)k, (float4*)kc,
        (const float4*)v, (float4*)vc,
        Wq, Wqp, Wk, Wkp, Wv, Wvp, Wo, Wop);

    GemmSet sq{qc, Wqp, bq, Qd};
    GemmSet sk{kc, Wkp, bk, K0};
    GemmSet sv{vc, Wvp, bv, V0};
    gemm_bias_kernel<<<dim3(D_MODEL / BN, N_ROWS / BM, 3), 256, GEMM_SMEM>>>(
        sq, sk, sv, 1);                                  // #2

    pack_kv_kernel<<<dim3(128, 16, 2), 256>>>(K0, Kp, V0, Vp);   // #3

    attn_kernel<<<dim3(N_SEQ / QTILE, N_HEADS, N_BATCH), 256, ATTN_SMEM>>>();  // #4

    GemmSet so{Cd, Wop, bo, out};
    gemm_bias_kernel<<<dim3(D_MODEL / BN, N_ROWS / BM, 1), 256, GEMM_SMEM>>>(
        so, so, so, 0);                                  // #5
}

// round 12
// speedup vs baseline: 1.1311x; 1.0549x over previous
#include <cuda_runtime.h>
#include <cstdint>
#include <cstddef>

#define D_MODEL 1024
#define N_BATCH 4
#define N_SEQ   2048
#define N_HEADS 16
#define D_HEAD  64
#define N_ROWS  (N_BATCH * N_SEQ)   // 8192

// Scratch (device-global: no allocations allowed in kernel_launch).
__device__ float g_Q  [(size_t)N_ROWS * D_MODEL];  // plain, tf32-rounded
__device__ float g_K0 [(size_t)N_ROWS * D_MODEL];  // plain K, tf32-rounded
__device__ float g_V0 [(size_t)N_ROWS * D_MODEL];  // plain V, tf32-rounded
__device__ float g_Kp [(size_t)N_ROWS * D_MODEL];  // packed K per head chunk
__device__ float g_Vp [(size_t)N_ROWS * D_MODEL];  // packed V per (tile,h) block
__device__ float g_CTX[(size_t)N_ROWS * D_MODEL];  // plain, tf32-rounded
// tf32-pre-rounded plain copies of inputs / weights
__device__ float g_qc[(size_t)N_ROWS * D_MODEL];
__device__ float g_kc[(size_t)N_ROWS * D_MODEL];
__device__ float g_vc[(size_t)N_ROWS * D_MODEL];
__device__ float g_Wqc[(size_t)D_MODEL * D_MODEL];
__device__ float g_Wkc[(size_t)D_MODEL * D_MODEL];
__device__ float g_Wvc[(size_t)D_MODEL * D_MODEL];
__device__ float g_Woc[(size_t)D_MODEL * D_MODEL];

// ---------------------------------------------------------------------------
// Helpers
// ---------------------------------------------------------------------------
__device__ __forceinline__ uint32_t f2tf32(float x) {
    uint32_t r;
    asm("cvt.rna.tf32.f32 %0, %1;" : "=r"(r) : "f"(x));
    return r;
}
__device__ __forceinline__ void mma_tf32(float d[4], const uint32_t a[4], const uint32_t b[2]) {
    asm volatile(
        "mma.sync.aligned.m16n8k8.row.col.f32.tf32.tf32.f32 "
        "{%0,%1,%2,%3}, {%4,%5,%6,%7}, {%8,%9}, {%0,%1,%2,%3};\n"
        : "+f"(d[0]), "+f"(d[1]), "+f"(d[2]), "+f"(d[3])
        : "r"(a[0]), "r"(a[1]), "r"(a[2]), "r"(a[3]), "r"(b[0]), "r"(b[1]));
}
__device__ __forceinline__ void cp16(uint32_t s, const void* g) {
    asm volatile("cp.async.cg.shared.global [%0], [%1], 16;\n" :: "r"(s), "l"(g));
}
__device__ __forceinline__ void cp_commit() { asm volatile("cp.async.commit_group;\n"); }
__device__ __forceinline__ void cp_wait0()  { asm volatile("cp.async.wait_group 0;\n"); }
__device__ __forceinline__ uint32_t smem_u32(const void* p) {
    uint32_t a;
    asm("{ .reg .u64 t; cvta.to.shared.u64 t, %1; cvt.u32.u64 %0, t; }"
        : "=r"(a) : "l"(p));
    return a;
}

// ---- packed f32x2 (Blackwell FFMA2 pipe) ----
__device__ __forceinline__ uint64_t pk2(float a, float b) {
    uint64_t r; asm("mov.b64 %0, {%1, %2};" : "=l"(r) : "f"(a), "f"(b)); return r;
}
__device__ __forceinline__ void upk2(uint64_t v, float& a, float& b) {
    asm("mov.b64 {%0, %1}, %2;" : "=f"(a), "=f"(b) : "l"(v));
}
__device__ __forceinline__ void upk2u(uint64_t v, uint32_t& a, uint32_t& b) {
    asm("mov.b64 {%0, %1}, %2;" : "=r"(a), "=r"(b) : "l"(v));
}
__device__ __forceinline__ uint64_t pk2u(uint32_t a, uint32_t b) {
    uint64_t r; asm("mov.b64 %0, {%1, %2};" : "=l"(r) : "r"(a), "r"(b)); return r;
}
__device__ __forceinline__ uint64_t pfma2(uint64_t a, uint64_t b, uint64_t c) {
    uint64_t r;
    asm("fma.rn.f32x2 %0, %1, %2, %3;" : "=l"(r) : "l"(a), "l"(b), "l"(c));
    return r;
}
__device__ __forceinline__ uint64_t padd2(uint64_t a, uint64_t b) {
    uint64_t r; asm("add.rn.f32x2 %0, %1, %2;" : "=l"(r) : "l"(a), "l"(b)); return r;
}
__device__ __forceinline__ uint64_t pmul2(uint64_t a, uint64_t b) {
    uint64_t r; asm("mul.rn.f32x2 %0, %1, %2;" : "=l"(r) : "l"(a), "l"(b)); return r;
}

// scalar exp(x) for x <= 0 with clamp (correction factors only). ~3e-6 rel.
__device__ __forceinline__ float fast_exp(float x) {
    float t = fmaxf(x * 1.4426950408889634f, -126.0f);
    float z = t + 12582912.0f;
    int  ki = __float_as_int(z) - 0x4B400000;
    float f = t - (z - 12582912.0f);
    float u = f * 0.6931471805599453f;
    float p = 1.0f + u * (1.0f + u * (0.5f + u * (0.16666667f +
              u * (0.041666668f + u * 0.008333334f))));
    return __int_as_float(__float_as_int(p) + (ki << 23));
}

// ---------------------------------------------------------------------------
// Fused prep (ONE launch): z = 0..2 input tf32 pre-round (q,k,v);
// z = 3..6 weight tf32 pre-round (plain layout — round-3 GEMM format).
// ---------------------------------------------------------------------------
__global__ void __launch_bounds__(256)
prep_kernel(const float4* q,  float4* qc,  const float4* k,  float4* kc,
            const float4* v,  float4* vc,
            const float4* Wq, float4* Wqc, const float4* Wk, float4* Wkc,
            const float4* Wv, float4* Wvc, const float4* Wo, float4* Woc)
{
    const int z = blockIdx.z;
    const float4* __restrict__ in;
    float4* __restrict__ out;
    int n4;
    if (z < 3) {
        in  = (z == 0) ? q : (z == 1) ? k : v;
        out = (z == 0) ? qc : (z == 1) ? kc : vc;
        n4  = N_ROWS * D_MODEL / 4;
    } else {
        in  = (z == 3) ? Wq : (z == 4) ? Wk : (z == 5) ? Wv : Wo;
        out = (z == 3) ? Wqc : (z == 4) ? Wkc : (z == 5) ? Wvc : Woc;
        n4  = D_MODEL * D_MODEL / 4;
    }
    for (int i = blockIdx.x * blockDim.x + threadIdx.x; i < n4;
         i += gridDim.x * blockDim.x) {
        float4 w = in[i];
        w.x = __uint_as_float(f2tf32(w.x));
        w.y = __uint_as_float(f2tf32(w.y));
        w.z = __uint_as_float(f2tf32(w.z));
        w.w = __uint_as_float(f2tf32(w.w));
        out[i] = w;
    }
}

// ---------------------------------------------------------------------------
// Fused K+V pack (ONE launch): z=0 K pack (grid-stride), z=1 V pack per
// (tile,h). Mappings identical to rounds 8-11 (bit-verified).
// ---------------------------------------------------------------------------
__global__ void __launch_bounds__(256)
pack_kv_kernel(const float* __restrict__ K0, float* __restrict__ Kp,
               const float* __restrict__ V0, float* __restrict__ Vp)
{
    __shared__ float sm[64][65];
    if (blockIdx.z == 0) {
        const int flat = blockIdx.y * gridDim.x + blockIdx.x;
        const int nthr = gridDim.x * gridDim.y * 256;
        const int total2 = N_ROWS * D_MODEL / 2;
        for (int i = flat * 256 + threadIdx.x; i < total2; i += nthr) {
            const int o = i * 2, chunk = o >> 6, p = o & 63;   // p even
            const int dh = ((p & 15) << 2) + (p >> 4);
            const float* base = K0 + (size_t)chunk * 64;
            *(float2*)(Kp + (size_t)chunk * 64 + p) =
                make_float2(base[dh], base[dh + 4]);
        }
    } else {
        const int tile = blockIdx.x, h = blockIdx.y;
        const int tid = threadIdx.x;
        const float* src = V0 + (size_t)tile * 64 * D_MODEL + h * 64;
        #pragma unroll
        for (int i = 0; i < 4; i++) {
            const int idx = tid + i * 256;
            const int rl = idx >> 4, c4 = (idx & 15) * 4;
            float4 w = *(const float4*)(src + (size_t)rl * D_MODEL + c4);
            sm[rl][c4] = w.x; sm[rl][c4 + 1] = w.y;
            sm[rl][c4 + 2] = w.z; sm[rl][c4 + 3] = w.w;
        }
        __syncthreads();
        float* dst = Vp + (size_t)(tile * 16 + h) * 4096;
        #pragma unroll
        for (int i = 0; i < 4; i++) {
            const int o = (tid + i * 256) * 4;
            float4 w;
            #pragma unroll
            for (int e = 0; e < 4; e++) {
                const int oo = o + e;
                const int tt = oo >> 10, dh = (oo >> 4) & 63, lo = oo & 15;
                const int rl = ((lo >> 1) << 3) + (tt << 1) + (lo & 1);
                ((float*)&w)[e] = sm[rl][dh];
            }
            *(float4*)(dst + o) = w;
        }
    }
}

// ---------------------------------------------------------------------------
// GEMM — ROUND-3 PROVEN VERSION, verbatim: plain tf32 A and W,
// BM=128 BN=128 BK=32, 256 threads (8 warps 4x2), warp tile 32x64,
// cp.async double-buffered, per-kk fragment loads, single barrier/k-tile.
// ---------------------------------------------------------------------------
#define BM 128
#define BN 128
#define BK 32
#define ASTR 36
#define BSTR 136
#define A_BUF (BM * ASTR)
#define B_BUF (BK * BSTR)
#define GEMM_SMEM ((2 * A_BUF + 2 * B_BUF) * 4)   // 71680 B

struct GemmSet { const float* A; const float* W; const float* bias; float* C; };

__global__ void __launch_bounds__(256)
gemm_bias_kernel(GemmSet s0, GemmSet s1, GemmSet s2, int round_out)
{
    const GemmSet& S = (blockIdx.z == 0) ? s0 : (blockIdx.z == 1) ? s1 : s2;
    const float* __restrict__ A    = S.A;
    const float* __restrict__ W    = S.W;
    const float* __restrict__ bias = S.bias;
    float* __restrict__ C          = S.C;

    extern __shared__ float smem[];
    float* As = smem;
    float* Bs = smem + 2 * A_BUF;
    const uint32_t sA = smem_u32(As);
    const uint32_t sB = smem_u32(Bs);

    const int tid  = threadIdx.x;
    const int warp = tid >> 5, lane = tid & 31;
    const int g = lane >> 2, t = lane & 3;
    const int wm = warp >> 1, wn = warp & 1;
    const int m_base = wm * 32, n_base = wn * 64;
    const int cta_m = blockIdx.y * BM;
    const int cta_n = blockIdx.x * BN;

    float acc[2][8][4];
    #pragma unroll
    for (int i = 0; i < 2; i++)
        #pragma unroll
        for (int j = 0; j < 8; j++)
            #pragma unroll
            for (int e = 0; e < 4; e++) acc[i][j][e] = 0.f;

    auto issue_loads = [&](int kt, int buf) {
        const float* Ag = A + (size_t)cta_m * D_MODEL + kt * BK;
        #pragma unroll
        for (int i = 0; i < 4; i++) {
            int idx = tid + i * 256;
            int r = idx >> 3, c = (idx & 7) * 4;
            cp16(sA + (uint32_t)(buf * A_BUF + r * ASTR + c) * 4,
                 Ag + (size_t)r * D_MODEL + c);
        }
        const float* Wg = W + (size_t)(kt * BK) * D_MODEL + cta_n;
        #pragma unroll
        for (int i = 0; i < 4; i++) {
            int idx = tid + i * 256;
            int r = idx >> 5, c = (idx & 31) * 4;
            cp16(sB + (uint32_t)(buf * B_BUF + r * BSTR + c) * 4,
                 Wg + (size_t)r * D_MODEL + c);
        }
        cp_commit();
    };

    issue_loads(0, 0);

    const int KT = D_MODEL / BK;  // 32
    for (int kt = 0; kt < KT; kt++) {
        cp_wait0();
        __syncthreads();
        if (kt + 1 < KT) issue_loads(kt + 1, (kt + 1) & 1);

        const float* Ab = As + (kt & 1) * A_BUF;
        const float* Bb = Bs + (kt & 1) * B_BUF;
        #pragma unroll
        for (int kk = 0; kk < 4; kk++) {
            const int k0 = kk * 8;
            uint32_t af[2][4], bf[8][2];
            #pragma unroll
            for (int mt = 0; mt < 2; mt++) {
                const int m0 = m_base + mt * 16;
                af[mt][0] = __float_as_uint(Ab[(m0 + g)     * ASTR + k0 + t]);
                af[mt][1] = __float_as_uint(Ab[(m0 + g + 8) * ASTR + k0 + t]);
                af[mt][2] = __float_as_uint(Ab[(m0 + g)     * ASTR + k0 + t + 4]);
                af[mt][3] = __float_as_uint(Ab[(m0 + g + 8) * ASTR + k0 + t + 4]);
            }
            #pragma unroll
            for (int nt = 0; nt < 8; nt++) {
                const int n0 = n_base + nt * 8;
                bf[nt][0] = __float_as_uint(Bb[(k0 + t)     * BSTR + n0 + g]);
                bf[nt][1] = __float_as_uint(Bb[(k0 + t + 4) * BSTR + n0 + g]);
            }
            #pragma unroll
            for (int mt = 0; mt < 2; mt++)
                #pragma unroll
                for (int nt = 0; nt < 8; nt++)
                    mma_tf32(acc[mt][nt], af[mt], bf[nt]);
        }
    }

    #pragma unroll
    for (int mt = 0; mt < 2; mt++) {
        #pragma unroll
        for (int nt = 0; nt < 8; nt++) {
            int r0 = cta_m + m_base + mt * 16 + g;
            int c0 = cta_n + n_base + nt * 8 + 2 * t;
            float b0 = bias[c0], b1 = bias[c0 + 1];
            float v00 = acc[mt][nt][0] + b0, v01 = acc[mt][nt][1] + b1;
            float v10 = acc[mt][nt][2] + b0, v11 = acc[mt][nt][3] + b1;
            if (round_out) {
                v00 = __uint_as_float(f2tf32(v00));
                v01 = __uint_as_float(f2tf32(v01));
                v10 = __uint_as_float(f2tf32(v10));
                v11 = __uint_as_float(f2tf32(v11));
            }
            *(float2*)(C + (size_t)r0 * D_MODEL + c0)       = make_float2(v00, v01);
            *(float2*)(C + (size_t)(r0 + 8) * D_MODEL + c0) = make_float2(v10, v11);
        }
    }
}

// ---------------------------------------------------------------------------
// Flash attention — byte-identical to rounds 9/10/11 (541 us measured).
// ---------------------------------------------------------------------------
#define QTILE 128
#define KSTG 5120
#define VSTG 5152
#define ATTN_SMEM ((2 * KSTG + 2 * VSTG) * 4)   // 82176 B

__global__ void __launch_bounds__(256, 2)
attn_kernel()
{
    extern __shared__ float sm[];
    float* Ks = sm;
    float* Vs = sm + 2 * KSTG;
    const uint32_t sK = smem_u32(Ks);
    const uint32_t sV = smem_u32(Vs);

    const int tid  = threadIdx.x;
    const int warp = tid >> 5, lane = tid & 31;
    const int g = lane >> 2, t = lane & 3;
    const int b = blockIdx.z, h = blockIdx.y;
    const int s0 = blockIdx.x * QTILE;
    const int q0 = warp * 16;

    {
        const float* Qg = g_Q + ((size_t)(b * N_SEQ + s0)) * D_MODEL + h * D_HEAD;
        #pragma unroll
        for (int i = 0; i < 8; i++) {
            int idx = tid + i * 256;
            int r = idx >> 4, c = idx & 15;
            cp16(sK + r * 272 + c * 16, Qg + (size_t)r * D_MODEL + c * 4);
        }
        cp_commit(); cp_wait0();
        __syncthreads();
    }
    uint32_t qf[8][4];
    #pragma unroll
    for (int kk = 0; kk < 8; kk++) {
        const int k0 = kk * 8;
        qf[kk][0] = __float_as_uint(Ks[(q0 + g)     * 68 + k0 + t]     * 0.125f);
        qf[kk][1] = __float_as_uint(Ks[(q0 + g + 8) * 68 + k0 + t]     * 0.125f);
        qf[kk][2] = __float_as_uint(Ks[(q0 + g)     * 68 + k0 + t + 4] * 0.125f);
        qf[kk][3] = __float_as_uint(Ks[(q0 + g + 8) * 68 + k0 + t + 4] * 0.125f);
    }
    __syncthreads();

    auto issue_kv = [&](int kt, int buf) {
        const float* Kg = g_Kp + ((size_t)(b * N_SEQ + kt * 64)) * D_MODEL + h * D_HEAD;
        const float* Vg = g_Vp + ((size_t)(((b * 32 + kt) << 4) + h)) * 4096;
        #pragma unroll
        for (int i = 0; i < 4; i++) {
            int idx = tid + i * 256;
            int r = idx >> 4, tt = (idx >> 2) & 3, c = idx & 3;
            cp16(sK + buf * 20480 + r * 320 + tt * 80 + c * 16,
                 Kg + (size_t)r * D_MODEL + tt * 16 + c * 4);
        }
        #pragma unroll
        for (int i = 0; i < 4; i++) {
            int idx = tid + i * 256;
            int tt = idx >> 8, n = (idx >> 2) & 63, c = idx & 3;
            cp16(sV + buf * 20608 + tt * 5152 + n * 80 + c * 16,
                 Vg + tt * 1024 + n * 16 + c * 4);
        }
        cp_commit();
    };

    float m0 = -1e30f, m1 = -1e30f, l0 = 0.f, l1 = 0.f;
    float o[8][4];
    #pragma unroll
    for (int dt = 0; dt < 8; dt++)
        #pragma unroll
        for (int e = 0; e < 4; e++) o[dt][e] = 0.f;

    issue_kv(0, 0);

    const int NT = N_SEQ / 64;
    for (int kt = 0; kt < NT; kt++) {
        cp_wait0();
        __syncthreads();
        if (kt + 1 < NT) issue_kv(kt + 1, (kt + 1) & 1);

        const float* Kb = Ks + (kt & 1) * KSTG;
        const float* Vb = Vs + (kt & 1) * VSTG;

        float s[8][4];
        #pragma unroll
        for (int nt = 0; nt < 8; nt++) {
            s[nt][0] = s[nt][1] = s[nt][2] = s[nt][3] = 0.f;
            const float4* kr = (const float4*)(Kb + (nt * 8 + g) * 80 + t * 20);
            float4 x0 = kr[0], x1 = kr[1], x2 = kr[2], x3 = kr[3];
            uint32_t kf[16] = {
                __float_as_uint(x0.x), __float_as_uint(x0.y),
                __float_as_uint(x0.z), __float_as_uint(x0.w),
                __float_as_uint(x1.x), __float_as_uint(x1.y),
                __float_as_uint(x1.z), __float_as_uint(x1.w),
                __float_as_uint(x2.x), __float_as_uint(x2.y),
                __float_as_uint(x2.z), __float_as_uint(x2.w),
                __float_as_uint(x3.x), __float_as_uint(x3.y),
                __float_as_uint(x3.z), __float_as_uint(x3.w)};
            #pragma unroll
            for (int ss = 0; ss < 8; ss++) {
                uint32_t b2[2] = {kf[2 * ss], kf[2 * ss + 1]};
                mma_tf32(s[nt], qf[ss], b2);
            }
        }

        float tm0 = -1e30f, tm1 = -1e30f;
        #pragma unroll
        for (int nt = 0; nt < 8; nt++) {
            tm0 = fmaxf(tm0, fmaxf(s[nt][0], s[nt][1]));
            tm1 = fmaxf(tm1, fmaxf(s[nt][2], s[nt][3]));
        }
        tm0 = fmaxf(tm0, __shfl_xor_sync(0xffffffffu, tm0, 1));
        tm0 = fmaxf(tm0, __shfl_xor_sync(0xffffffffu, tm0, 2));
        tm1 = fmaxf(tm1, __shfl_xor_sync(0xffffffffu, tm1, 1));
        tm1 = fmaxf(tm1, __shfl_xor_sync(0xffffffffu, tm1, 2));

        const float nm0 = fmaxf(m0, tm0), nm1 = fmaxf(m1, tm1);
        const bool changed = (nm0 != m0) || (nm1 != m1);

        const float L2E = 1.4426950408889634f;
        const uint64_t L2E2  = pk2(L2E, L2E);
        const uint64_t NM0_2 = pk2(-nm0 * L2E, -nm0 * L2E);
        const uint64_t NM1_2 = pk2(-nm1 * L2E, -nm1 * L2E);
        const uint64_t MAG2  = pk2(12582912.0f, 12582912.0f);
        const uint64_t NMAG2 = pk2(-12582912.0f, -12582912.0f);
        const uint64_t NEG1  = pk2(-1.0f, -1.0f);
        const uint64_t PC0   = pk2(1.0f, 1.0f);
        const uint64_t PC1   = pk2(0.6931471805599453f, 0.6931471805599453f);
        const uint64_t PC2   = pk2(0.2402265069591007f, 0.2402265069591007f);
        const uint64_t PC3   = pk2(0.0555041086648216f, 0.0555041086648216f);
        const uint64_t PC4   = pk2(0.0096181291076285f, 0.0096181291076285f);

        auto exp2p = [&](uint64_t t2) -> uint64_t {
            uint64_t z2  = padd2(t2, MAG2);
            uint64_t km2 = padd2(z2, NMAG2);
            uint64_t f2  = pfma2(km2, NEG1, t2);
            uint64_t r   = pfma2(PC4, f2, PC3);
            r = pfma2(r, f2, PC2);
            r = pfma2(r, f2, PC1);
            r = pfma2(r, f2, PC0);
            uint32_t zl, zh;
            upk2u(z2, zl, zh);
            uint32_t sl = (zl << 23) + 0x3F800000u;
            uint32_t sh = (zh << 23) + 0x3F800000u;
            return pmul2(r, pk2u(sl, sh));
        };

        uint64_t rsA = pk2(0.f, 0.f), rsB = pk2(0.f, 0.f);
        #pragma unroll
        for (int nt = 0; nt < 8; nt++) {
            uint64_t d0 = pk2(s[nt][0], s[nt][1]);
            uint64_t d1 = pk2(s[nt][2], s[nt][3]);
            uint64_t p0 = exp2p(pfma2(d0, L2E2, NM0_2));
            uint64_t p1 = exp2p(pfma2(d1, L2E2, NM1_2));
            rsA = padd2(rsA, p0);
            rsB = padd2(rsB, p1);
            float a0, a1;
            upk2(p0, a0, a1);
            s[nt][0] = __uint_as_float(f2tf32(a0));
            s[nt][1] = __uint_as_float(f2tf32(a1));
            upk2(p1, a0, a1);
            s[nt][2] = __uint_as_float(f2tf32(a0));
            s[nt][3] = __uint_as_float(f2tf32(a1));
        }
        float ra, rb;
        upk2(rsA, ra, rb);
        float rs0 = ra + rb;
        upk2(rsB, ra, rb);
        float rs1 = ra + rb;
        rs0 += __shfl_xor_sync(0xffffffffu, rs0, 1);
        rs0 += __shfl_xor_sync(0xffffffffu, rs0, 2);
        rs1 += __shfl_xor_sync(0xffffffffu, rs1, 1);
        rs1 += __shfl_xor_sync(0xffffffffu, rs1, 2);

        if (__any_sync(0xffffffffu, changed)) {
            const float c0 = fast_exp(m0 - nm0), c1 = fast_exp(m1 - nm1);
            l0 = l0 * c0 + rs0;
            l1 = l1 * c1 + rs1;
            #pragma unroll
            for (int dt = 0; dt < 8; dt++) {
                o[dt][0] *= c0; o[dt][1] *= c0;
                o[dt][2] *= c1; o[dt][3] *= c1;
            }
        } else {
            l0 += rs0;
            l1 += rs1;
        }
        m0 = nm0; m1 = nm1;

        #pragma unroll
        for (int dt = 0; dt < 8; dt++) {
            const float4* vr = (const float4*)(Vb + t * 1288 + (dt * 8 + g) * 20);
            float4 y0 = vr[0], y1 = vr[1], y2 = vr[2], y3 = vr[3];
            uint32_t vf[16] = {
                __float_as_uint(y0.x), __float_as_uint(y0.y),
                __float_as_uint(y0.z), __float_as_uint(y0.w),
                __float_as_uint(y1.x), __float_as_uint(y1.y),
                __float_as_uint(y1.z), __float_as_uint(y1.w),
                __float_as_uint(y2.x), __float_as_uint(y2.y),
                __float_as_uint(y2.z), __float_as_uint(y2.w),
                __float_as_uint(y3.x), __float_as_uint(y3.y),
                __float_as_uint(y3.z), __float_as_uint(y3.w)};
            #pragma unroll
            for (int kk = 0; kk < 8; kk++) {
                uint32_t a4[4] = {__float_as_uint(s[kk][0]), __float_as_uint(s[kk][2]),
                                  __float_as_uint(s[kk][1]), __float_as_uint(s[kk][3])};
                uint32_t b2[2] = {vf[2 * kk], vf[2 * kk + 1]};
                mma_tf32(o[dt], a4, b2);
            }
        }
    }

    const float inv0 = 1.0f / l0, inv1 = 1.0f / l1;
    float* Cg = g_CTX + ((size_t)(b * N_SEQ + s0 + q0)) * D_MODEL + h * D_HEAD;
    #pragma unroll
    for (int dt = 0; dt < 8; dt++) {
        const int cc = dt * 8 + 2 * t;
        *(float2*)(Cg + (size_t)g * D_MODEL + cc) = make_float2(
            __uint_as_float(f2tf32(o[dt][0] * inv0)),
            __uint_as_float(f2tf32(o[dt][1] * inv0)));
        *(float2*)(Cg + (size_t)(g + 8) * D_MODEL + cc) = make_float2(
            __uint_as_float(f2tf32(o[dt][2] * inv1)),
            __uint_as_float(f2tf32(o[dt][3] * inv1)));
    }
}

// ---------------------------------------------------------------------------
extern "C" void kernel_launch(void* const* d_in, const int* in_sizes, int n_in,
                              void* d_out, int out_size)
{
    (void)in_sizes; (void)n_in; (void)out_size;
    const float* q  = (const float*)d_in[0];
    const float* k  = (const float*)d_in[1];
    const float* v  = (const float*)d_in[2];
    const float* Wq = (const float*)d_in[3];
    const float* bq = (const float*)d_in[4];
    const float* Wk = (const float*)d_in[5];
    const float* bk = (const float*)d_in[6];
    const float* Wv = (const float*)d_in[7];
    const float* bv = (const float*)d_in[8];
    const float* Wo = (const float*)d_in[9];
    const float* bo = (const float*)d_in[10];
    float* out = (float*)d_out;

    float *Qd, *K0, *V0, *Kp, *Vp, *Cd, *qc, *kc, *vc, *Wqc, *Wkc, *Wvc, *Woc;
    cudaGetSymbolAddress((void**)&Qd,  g_Q);
    cudaGetSymbolAddress((void**)&K0,  g_K0);
    cudaGetSymbolAddress((void**)&V0,  g_V0);
    cudaGetSymbolAddress((void**)&Kp,  g_Kp);
    cudaGetSymbolAddress((void**)&Vp,  g_Vp);
    cudaGetSymbolAddress((void**)&Cd,  g_CTX);
    cudaGetSymbolAddress((void**)&qc,  g_qc);
    cudaGetSymbolAddress((void**)&kc,  g_kc);
    cudaGetSymbolAddress((void**)&vc,  g_vc);
    cudaGetSymbolAddress((void**)&Wqc, g_Wqc);
    cudaGetSymbolAddress((void**)&Wkc, g_Wkc);
    cudaGetSymbolAddress((void**)&Wvc, g_Wvc);
    cudaGetSymbolAddress((void**)&Woc, g_Woc);

    cudaFuncSetAttribute(gemm_bias_kernel,
                         cudaFuncAttributeMaxDynamicSharedMemorySize, GEMM_SMEM);
    cudaFuncSetAttribute(attn_kernel,
                         cudaFuncAttributeMaxDynamicSharedMemorySize, ATTN_SMEM);

    // attn stays launch #4 (the slot ncu captures).
    prep_kernel<<<dim3(1024, 1, 7), 256>>>(              // #1
        (const float4*)q, (float4*)qc, (const float4*)k, (float4*)kc,
        (const float4*)v, (float4*)vc,
        (const float4*)Wq, (float4*)Wqc, (const float4*)Wk, (float4*)Wkc,
        (const float4*)Wv, (float4*)Wvc, (const float4*)Wo, (float4*)Woc);

    GemmSet sq{qc, Wqc, bq, Qd};
    GemmSet sk{kc, Wkc, bk, K0};
    GemmSet sv{vc, Wvc, bv, V0};
    gemm_bias_kernel<<<dim3(D_MODEL / BN, N_ROWS / BM, 3), 256, GEMM_SMEM>>>(
        sq, sk, sv, 1);                                  // #2

    pack_kv_kernel<<<dim3(128, 16, 2), 256>>>(K0, Kp, V0, Vp);   // #3

    attn_kernel<<<dim3(N_SEQ / QTILE, N_HEADS, N_BATCH), 256, ATTN_SMEM>>>();  // #4

    GemmSet so{Cd, Woc, bo, out};
    gemm_bias_kernel<<<dim3(D_MODEL / BN, N_ROWS / BM, 1), 256, GEMM_SMEM>>>(
        so, so, so, 0);                                  // #5
}

// round 14
// speedup vs baseline: 1.1495x; 1.0162x over previous
#include <cuda_runtime.h>
#include <cstdint>
#include <cstddef>

#define D_MODEL 1024
#define N_BATCH 4
#define N_SEQ   2048
#define N_HEADS 16
#define D_HEAD  64
#define N_ROWS  (N_BATCH * N_SEQ)   // 8192

// Scratch (device-global: no allocations allowed in kernel_launch).
__device__ float g_Q  [(size_t)N_ROWS * D_MODEL];  // plain, tf32-rounded
__device__ float g_K0 [(size_t)N_ROWS * D_MODEL];  // plain K, tf32-rounded
__device__ float g_V0 [(size_t)N_ROWS * D_MODEL];  // plain V, tf32-rounded
__device__ float g_Kp [(size_t)N_ROWS * D_MODEL];  // packed K per head chunk
__device__ float g_Vp [(size_t)N_ROWS * D_MODEL];  // packed V per (tile,h) block
__device__ float g_CTX[(size_t)N_ROWS * D_MODEL];  // plain, tf32-rounded
// tf32-pre-rounded plain copies of inputs / weights
__device__ float g_qc[(size_t)N_ROWS * D_MODEL];
__device__ float g_kc[(size_t)N_ROWS * D_MODEL];
__device__ float g_vc[(size_t)N_ROWS * D_MODEL];
__device__ float g_Wqc[(size_t)D_MODEL * D_MODEL];
__device__ float g_Wkc[(size_t)D_MODEL * D_MODEL];
__device__ float g_Wvc[(size_t)D_MODEL * D_MODEL];
__device__ float g_Woc[(size_t)D_MODEL * D_MODEL];

// ---------------------------------------------------------------------------
// Helpers
// ---------------------------------------------------------------------------
__device__ __forceinline__ uint32_t f2tf32(float x) {
    uint32_t r;
    asm("cvt.rna.tf32.f32 %0, %1;" : "=r"(r) : "f"(x));
    return r;
}
__device__ __forceinline__ void mma_tf32(float d[4], const uint32_t a[4], const uint32_t b[2]) {
    asm volatile(
        "mma.sync.aligned.m16n8k8.row.col.f32.tf32.tf32.f32 "
        "{%0,%1,%2,%3}, {%4,%5,%6,%7}, {%8,%9}, {%0,%1,%2,%3};\n"
        : "+f"(d[0]), "+f"(d[1]), "+f"(d[2]), "+f"(d[3])
        : "r"(a[0]), "r"(a[1]), "r"(a[2]), "r"(a[3]), "r"(b[0]), "r"(b[1]));
}
__device__ __forceinline__ void cp16(uint32_t s, const void* g) {
    asm volatile("cp.async.cg.shared.global [%0], [%1], 16;\n" :: "r"(s), "l"(g));
}
__device__ __forceinline__ void cp_commit() { asm volatile("cp.async.commit_group;\n"); }
__device__ __forceinline__ void cp_wait0()  { asm volatile("cp.async.wait_group 0;\n"); }
__device__ __forceinline__ uint32_t smem_u32(const void* p) {
    uint32_t a;
    asm("{ .reg .u64 t; cvta.to.shared.u64 t, %1; cvt.u32.u64 %0, t; }"
        : "=r"(a) : "l"(p));
    return a;
}

// ---- packed f32x2 (Blackwell FFMA2 pipe) ----
__device__ __forceinline__ uint64_t pk2(float a, float b) {
    uint64_t r; asm("mov.b64 %0, {%1, %2};" : "=l"(r) : "f"(a), "f"(b)); return r;
}
__device__ __forceinline__ void upk2(uint64_t v, float& a, float& b) {
    asm("mov.b64 {%0, %1}, %2;" : "=f"(a), "=f"(b) : "l"(v));
}
__device__ __forceinline__ void upk2u(uint64_t v, uint32_t& a, uint32_t& b) {
    asm("mov.b64 {%0, %1}, %2;" : "=r"(a), "=r"(b) : "l"(v));
}
__device__ __forceinline__ uint64_t pk2u(uint32_t a, uint32_t b) {
    uint64_t r; asm("mov.b64 %0, {%1, %2};" : "=l"(r) : "r"(a), "r"(b)); return r;
}
__device__ __forceinline__ uint64_t pfma2(uint64_t a, uint64_t b, uint64_t c) {
    uint64_t r;
    asm("fma.rn.f32x2 %0, %1, %2, %3;" : "=l"(r) : "l"(a), "l"(b), "l"(c));
    return r;
}
__device__ __forceinline__ uint64_t padd2(uint64_t a, uint64_t b) {
    uint64_t r; asm("add.rn.f32x2 %0, %1, %2;" : "=l"(r) : "l"(a), "l"(b)); return r;
}
__device__ __forceinline__ uint64_t pmul2(uint64_t a, uint64_t b) {
    uint64_t r; asm("mul.rn.f32x2 %0, %1, %2;" : "=l"(r) : "l"(a), "l"(b)); return r;
}

// scalar exp(x) for x <= 0 with clamp (correction factors only). ~3e-6 rel.
__device__ __forceinline__ float fast_exp(float x) {
    float t = fmaxf(x * 1.4426950408889634f, -126.0f);
    float z = t + 12582912.0f;
    int  ki = __float_as_int(z) - 0x4B400000;
    float f = t - (z - 12582912.0f);
    float u = f * 0.6931471805599453f;
    float p = 1.0f + u * (1.0f + u * (0.5f + u * (0.16666667f +
              u * (0.041666668f + u * 0.008333334f))));
    return __int_as_float(__float_as_int(p) + (ki << 23));
}

// ---------------------------------------------------------------------------
// Fused prep (ONE launch): z = 0..2 input tf32 pre-round (q,k,v);
// z = 3..6 weight tf32 pre-round (plain layout).
// ---------------------------------------------------------------------------
__global__ void __launch_bounds__(256)
prep_kernel(const float4* q,  float4* qc,  const float4* k,  float4* kc,
            const float4* v,  float4* vc,
            const float4* Wq, float4* Wqc, const float4* Wk, float4* Wkc,
            const float4* Wv, float4* Wvc, const float4* Wo, float4* Woc)
{
    const int z = blockIdx.z;
    const float4* __restrict__ in;
    float4* __restrict__ out;
    int n4;
    if (z < 3) {
        in  = (z == 0) ? q : (z == 1) ? k : v;
        out = (z == 0) ? qc : (z == 1) ? kc : vc;
        n4  = N_ROWS * D_MODEL / 4;
    } else {
        in  = (z == 3) ? Wq : (z == 4) ? Wk : (z == 5) ? Wv : Wo;
        out = (z == 3) ? Wqc : (z == 4) ? Wkc : (z == 5) ? Wvc : Woc;
        n4  = D_MODEL * D_MODEL / 4;
    }
    for (int i = blockIdx.x * blockDim.x + threadIdx.x; i < n4;
         i += gridDim.x * blockDim.x) {
        float4 w = in[i];
        w.x = __uint_as_float(f2tf32(w.x));
        w.y = __uint_as_float(f2tf32(w.y));
        w.z = __uint_as_float(f2tf32(w.z));
        w.w = __uint_as_float(f2tf32(w.w));
        out[i] = w;
    }
}

// ---------------------------------------------------------------------------
// Fused K+V pack (ONE launch): z=0 K pack, z=1 V pack (bit-verified maps).
// ---------------------------------------------------------------------------
__global__ void __launch_bounds__(256)
pack_kv_kernel(const float* __restrict__ K0, float* __restrict__ Kp,
               const float* __restrict__ V0, float* __restrict__ Vp)
{
    __shared__ float sm[64][65];
    if (blockIdx.z == 0) {
        const int flat = blockIdx.y * gridDim.x + blockIdx.x;
        const int nthr = gridDim.x * gridDim.y * 256;
        const int total2 = N_ROWS * D_MODEL / 2;
        for (int i = flat * 256 + threadIdx.x; i < total2; i += nthr) {
            const int o = i * 2, chunk = o >> 6, p = o & 63;   // p even
            const int dh = ((p & 15) << 2) + (p >> 4);
            const float* base = K0 + (size_t)chunk * 64;
            *(float2*)(Kp + (size_t)chunk * 64 + p) =
                make_float2(base[dh], base[dh + 4]);
        }
    } else {
        const int tile = blockIdx.x, h = blockIdx.y;
        const int tid = threadIdx.x;
        const float* src = V0 + (size_t)tile * 64 * D_MODEL + h * 64;
        #pragma unroll
        for (int i = 0; i < 4; i++) {
            const int idx = tid + i * 256;
            const int rl = idx >> 4, c4 = (idx & 15) * 4;
            float4 w = *(const float4*)(src + (size_t)rl * D_MODEL + c4);
            sm[rl][c4] = w.x; sm[rl][c4 + 1] = w.y;
            sm[rl][c4 + 2] = w.z; sm[rl][c4 + 3] = w.w;
        }
        __syncthreads();
        float* dst = Vp + (size_t)(tile * 16 + h) * 4096;
        #pragma unroll
        for (int i = 0; i < 4; i++) {
            const int o = (tid + i * 256) * 4;
            float4 w;
            #pragma unroll
            for (int e = 0; e < 4; e++) {
                const int oo = o + e;
                const int tt = oo >> 10, dh = (oo >> 4) & 63, lo = oo & 15;
                const int rl = ((lo >> 1) << 3) + (tt << 1) + (lo & 1);
                ((float*)&w)[e] = sm[rl][dh];
            }
            *(float4*)(dst + o) = w;
        }
    }
}

// ---------------------------------------------------------------------------
// GEMM — ROUND-3 PROVEN VERSION (frozen).
// ---------------------------------------------------------------------------
#define BM 128
#define BN 128
#define BK 32
#define ASTR 36
#define BSTR 136
#define A_BUF (BM * ASTR)
#define B_BUF (BK * BSTR)
#define GEMM_SMEM ((2 * A_BUF + 2 * B_BUF) * 4)   // 71680 B

struct GemmSet { const float* A; const float* W; const float* bias; float* C; };

__global__ void __launch_bounds__(256)
gemm_bias_kernel(GemmSet s0, GemmSet s1, GemmSet s2, int round_out)
{
    const GemmSet& S = (blockIdx.z == 0) ? s0 : (blockIdx.z == 1) ? s1 : s2;
    const float* __restrict__ A    = S.A;
    const float* __restrict__ W    = S.W;
    const float* __restrict__ bias = S.bias;
    float* __restrict__ C          = S.C;

    extern __shared__ float smem[];
    float* As = smem;
    float* Bs = smem + 2 * A_BUF;
    const uint32_t sA = smem_u32(As);
    const uint32_t sB = smem_u32(Bs);

    const int tid  = threadIdx.x;
    const int warp = tid >> 5, lane = tid & 31;
    const int g = lane >> 2, t = lane & 3;
    const int wm = warp >> 1, wn = warp & 1;
    const int m_base = wm * 32, n_base = wn * 64;
    const int cta_m = blockIdx.y * BM;
    const int cta_n = blockIdx.x * BN;

    float acc[2][8][4];
    #pragma unroll
    for (int i = 0; i < 2; i++)
        #pragma unroll
        for (int j = 0; j < 8; j++)
            #pragma unroll
            for (int e = 0; e < 4; e++) acc[i][j][e] = 0.f;

    auto issue_loads = [&](int kt, int buf) {
        const float* Ag = A + (size_t)cta_m * D_MODEL + kt * BK;
        #pragma unroll
        for (int i = 0; i < 4; i++) {
            int idx = tid + i * 256;
            int r = idx >> 3, c = (idx & 7) * 4;
            cp16(sA + (uint32_t)(buf * A_BUF + r * ASTR + c) * 4,
                 Ag + (size_t)r * D_MODEL + c);
        }
        const float* Wg = W + (size_t)(kt * BK) * D_MODEL + cta_n;
        #pragma unroll
        for (int i = 0; i < 4; i++) {
            int idx = tid + i * 256;
            int r = idx >> 5, c = (idx & 31) * 4;
            cp16(sB + (uint32_t)(buf * B_BUF + r * BSTR + c) * 4,
                 Wg + (size_t)r * D_MODEL + c);
        }
        cp_commit();
    };

    issue_loads(0, 0);

    const int KT = D_MODEL / BK;  // 32
    for (int kt = 0; kt < KT; kt++) {
        cp_wait0();
        __syncthreads();
        if (kt + 1 < KT) issue_loads(kt + 1, (kt + 1) & 1);

        const float* Ab = As + (kt & 1) * A_BUF;
        const float* Bb = Bs + (kt & 1) * B_BUF;
        #pragma unroll
        for (int kk = 0; kk < 4; kk++) {
            const int k0 = kk * 8;
            uint32_t af[2][4], bf[8][2];
            #pragma unroll
            for (int mt = 0; mt < 2; mt++) {
                const int m0 = m_base + mt * 16;
                af[mt][0] = __float_as_uint(Ab[(m0 + g)     * ASTR + k0 + t]);
                af[mt][1] = __float_as_uint(Ab[(m0 + g + 8) * ASTR + k0 + t]);
                af[mt][2] = __float_as_uint(Ab[(m0 + g)     * ASTR + k0 + t + 4]);
                af[mt][3] = __float_as_uint(Ab[(m0 + g + 8) * ASTR + k0 + t + 4]);
            }
            #pragma unroll
            for (int nt = 0; nt < 8; nt++) {
                const int n0 = n_base + nt * 8;
                bf[nt][0] = __float_as_uint(Bb[(k0 + t)     * BSTR + n0 + g]);
                bf[nt][1] = __float_as_uint(Bb[(k0 + t + 4) * BSTR + n0 + g]);
            }
            #pragma unroll
            for (int mt = 0; mt < 2; mt++)
                #pragma unroll
                for (int nt = 0; nt < 8; nt++)
                    mma_tf32(acc[mt][nt], af[mt], bf[nt]);
        }
    }

    #pragma unroll
    for (int mt = 0; mt < 2; mt++) {
        #pragma unroll
        for (int nt = 0; nt < 8; nt++) {
            int r0 = cta_m + m_base + mt * 16 + g;
            int c0 = cta_n + n_base + nt * 8 + 2 * t;
            float b0 = bias[c0], b1 = bias[c0 + 1];
            float v00 = acc[mt][nt][0] + b0, v01 = acc[mt][nt][1] + b1;
            float v10 = acc[mt][nt][2] + b0, v11 = acc[mt][nt][3] + b1;
            if (round_out) {
                v00 = __uint_as_float(f2tf32(v00));
                v01 = __uint_as_float(f2tf32(v01));
                v10 = __uint_as_float(f2tf32(v10));
                v11 = __uint_as_float(f2tf32(v11));
            }
            *(float2*)(C + (size_t)r0 * D_MODEL + c0)       = make_float2(v00, v01);
            *(float2*)(C + (size_t)(r0 + 8) * D_MODEL + c0) = make_float2(v10, v11);
        }
    }
}

// ---------------------------------------------------------------------------
// Flash attention. Round-12 base; CHANGE: o/l rescale hoisted before exp, and
// exp fused with PV per kk-pair so FMA-pipe exp of block kkp+1 overlaps the
// tensor-pipe mmas of block kkp (breaks the per-tile phase convoy).
// P accumulation order per dt unchanged (kk ascending) -> bit-identical PV.
// ---------------------------------------------------------------------------
#define QTILE 128
#define KSTG 5120
#define VSTG 5152
#define ATTN_SMEM ((2 * KSTG + 2 * VSTG) * 4)   // 82176 B

__global__ void __launch_bounds__(256, 2)
attn_kernel()
{
    extern __shared__ float sm[];
    float* Ks = sm;
    float* Vs = sm + 2 * KSTG;
    const uint32_t sK = smem_u32(Ks);
    const uint32_t sV = smem_u32(Vs);

    const int tid  = threadIdx.x;
    const int warp = tid >> 5, lane = tid & 31;
    const int g = lane >> 2, t = lane & 3;
    const int b = blockIdx.z, h = blockIdx.y;
    const int s0 = blockIdx.x * QTILE;
    const int q0 = warp * 16;

    {
        const float* Qg = g_Q + ((size_t)(b * N_SEQ + s0)) * D_MODEL + h * D_HEAD;
        #pragma unroll
        for (int i = 0; i < 8; i++) {
            int idx = tid + i * 256;
            int r = idx >> 4, c = idx & 15;
            cp16(sK + r * 272 + c * 16, Qg + (size_t)r * D_MODEL + c * 4);
        }
        cp_commit(); cp_wait0();
        __syncthreads();
    }
    uint32_t qf[8][4];
    #pragma unroll
    for (int kk = 0; kk < 8; kk++) {
        const int k0 = kk * 8;
        qf[kk][0] = __float_as_uint(Ks[(q0 + g)     * 68 + k0 + t]     * 0.125f);
        qf[kk][1] = __float_as_uint(Ks[(q0 + g + 8) * 68 + k0 + t]     * 0.125f);
        qf[kk][2] = __float_as_uint(Ks[(q0 + g)     * 68 + k0 + t + 4] * 0.125f);
        qf[kk][3] = __float_as_uint(Ks[(q0 + g + 8) * 68 + k0 + t + 4] * 0.125f);
    }
    __syncthreads();

    auto issue_kv = [&](int kt, int buf) {
        const float* Kg = g_Kp + ((size_t)(b * N_SEQ + kt * 64)) * D_MODEL + h * D_HEAD;
        const float* Vg = g_Vp + ((size_t)(((b * 32 + kt) << 4) + h)) * 4096;
        #pragma unroll
        for (int i = 0; i < 4; i++) {
            int idx = tid + i * 256;
            int r = idx >> 4, tt = (idx >> 2) & 3, c = idx & 3;
            cp16(sK + buf * 20480 + r * 320 + tt * 80 + c * 16,
                 Kg + (size_t)r * D_MODEL + tt * 16 + c * 4);
        }
        #pragma unroll
        for (int i = 0; i < 4; i++) {
            int idx = tid + i * 256;
            int tt = idx >> 8, n = (idx >> 2) & 63, c = idx & 3;
            cp16(sV + buf * 20608 + tt * 5152 + n * 80 + c * 16,
                 Vg + tt * 1024 + n * 16 + c * 4);
        }
        cp_commit();
    };

    float m0 = -1e30f, m1 = -1e30f, l0 = 0.f, l1 = 0.f;
    float o[8][4];
    #pragma unroll
    for (int dt = 0; dt < 8; dt++)
        #pragma unroll
        for (int e = 0; e < 4; e++) o[dt][e] = 0.f;

    issue_kv(0, 0);

    const int NT = N_SEQ / 64;
    for (int kt = 0; kt < NT; kt++) {
        cp_wait0();
        __syncthreads();
        if (kt + 1 < NT) issue_kv(kt + 1, (kt + 1) & 1);

        const float* Kb = Ks + (kt & 1) * KSTG;
        const float* Vb = Vs + (kt & 1) * VSTG;

        // ---- S = (Q/8) K^T
        float s[8][4];
        #pragma unroll
        for (int nt = 0; nt < 8; nt++) {
            s[nt][0] = s[nt][1] = s[nt][2] = s[nt][3] = 0.f;
            const float4* kr = (const float4*)(Kb + (nt * 8 + g) * 80 + t * 20);
            float4 x0 = kr[0], x1 = kr[1], x2 = kr[2], x3 = kr[3];
            uint32_t kf[16] = {
                __float_as_uint(x0.x), __float_as_uint(x0.y),
                __float_as_uint(x0.z), __float_as_uint(x0.w),
                __float_as_uint(x1.x), __float_as_uint(x1.y),
                __float_as_uint(x1.z), __float_as_uint(x1.w),
                __float_as_uint(x2.x), __float_as_uint(x2.y),
                __float_as_uint(x2.z), __float_as_uint(x2.w),
                __float_as_uint(x3.x), __float_as_uint(x3.y),
                __float_as_uint(x3.z), __float_as_uint(x3.w)};
            #pragma unroll
            for (int ss = 0; ss < 8; ss++) {
                uint32_t b2[2] = {kf[2 * ss], kf[2 * ss + 1]};
                mma_tf32(s[nt], qf[ss], b2);
            }
        }

        // ---- row max
        float tm0 = -1e30f, tm1 = -1e30f;
        #pragma unroll
        for (int nt = 0; nt < 8; nt++) {
            tm0 = fmaxf(tm0, fmaxf(s[nt][0], s[nt][1]));
            tm1 = fmaxf(tm1, fmaxf(s[nt][2], s[nt][3]));
        }
        tm0 = fmaxf(tm0, __shfl_xor_sync(0xffffffffu, tm0, 1));
        tm0 = fmaxf(tm0, __shfl_xor_sync(0xffffffffu, tm0, 2));
        tm1 = fmaxf(tm1, __shfl_xor_sync(0xffffffffu, tm1, 1));
        tm1 = fmaxf(tm1, __shfl_xor_sync(0xffffffffu, tm1, 2));

        const float nm0 = fmaxf(m0, tm0), nm1 = fmaxf(m1, tm1);
        const bool changed = (nm0 != m0) || (nm1 != m1);

        // ---- rescale BEFORE exp (depends only on new max; vote-skippable)
        if (__any_sync(0xffffffffu, changed)) {
            const float c0 = fast_exp(m0 - nm0), c1 = fast_exp(m1 - nm1);
            l0 *= c0; l1 *= c1;
            #pragma unroll
            for (int dt = 0; dt < 8; dt++) {
                o[dt][0] *= c0; o[dt][1] *= c0;
                o[dt][2] *= c1; o[dt][3] *= c1;
            }
        }
        m0 = nm0; m1 = nm1;

        // ---- fused exp + PV: per kk-pair, exp (FMA pipe) then mma (tensor)
        const float L2E = 1.4426950408889634f;
        const uint64_t L2E2  = pk2(L2E, L2E);
        const uint64_t NM0_2 = pk2(-nm0 * L2E, -nm0 * L2E);
        const uint64_t NM1_2 = pk2(-nm1 * L2E, -nm1 * L2E);
        const uint64_t MAG2  = pk2(12582912.0f, 12582912.0f);
        const uint64_t NMAG2 = pk2(-12582912.0f, -12582912.0f);
        const uint64_t NEG1  = pk2(-1.0f, -1.0f);
        const uint64_t PC0   = pk2(1.0f, 1.0f);
        const uint64_t PC1   = pk2(0.6931471805599453f, 0.6931471805599453f);
        const uint64_t PC2   = pk2(0.2402265069591007f, 0.2402265069591007f);
        const uint64_t PC3   = pk2(0.0555041086648216f, 0.0555041086648216f);
        const uint64_t PC4   = pk2(0.0096181291076285f, 0.0096181291076285f);

        auto exp2p = [&](uint64_t t2) -> uint64_t {
            uint64_t z2  = padd2(t2, MAG2);
            uint64_t km2 = padd2(z2, NMAG2);
            uint64_t f2  = pfma2(km2, NEG1, t2);
            uint64_t r   = pfma2(PC4, f2, PC3);
            r = pfma2(r, f2, PC2);
            r = pfma2(r, f2, PC1);
            r = pfma2(r, f2, PC0);
            uint32_t zl, zh;
            upk2u(z2, zl, zh);
            uint32_t sl = (zl << 23) + 0x3F800000u;
            uint32_t sh = (zh << 23) + 0x3F800000u;
            return pmul2(r, pk2u(sl, sh));
        };

        uint64_t rsA = pk2(0.f, 0.f), rsB = pk2(0.f, 0.f);
        #pragma unroll
        for (int kkp = 0; kkp < 4; kkp++) {
            uint32_t a4[2][4];
            #pragma unroll
            for (int e = 0; e < 2; e++) {
                const int kk = 2 * kkp + e;
                uint64_t p0 = exp2p(pfma2(pk2(s[kk][0], s[kk][1]), L2E2, NM0_2));
                uint64_t p1 = exp2p(pfma2(pk2(s[kk][2], s[kk][3]), L2E2, NM1_2));
                rsA = padd2(rsA, p0);
                rsB = padd2(rsB, p1);
                float a0, a1, b0v, b1v;
                upk2(p0, a0, a1);
                upk2(p1, b0v, b1v);
                a4[e][0] = f2tf32(a0);    // row g,   col even
                a4[e][1] = f2tf32(b0v);   // row g+8, col even  (sigma reorder)
                a4[e][2] = f2tf32(a1);    // row g,   col odd
                a4[e][3] = f2tf32(b1v);   // row g+8, col odd
            }
            #pragma unroll
            for (int dt = 0; dt < 8; dt++) {
                const float4* vr = (const float4*)
                    (Vb + t * 1288 + (dt * 8 + g) * 20 + kkp * 4);
                float4 y = vr[0];
                uint32_t b2a[2] = {__float_as_uint(y.x), __float_as_uint(y.y)};
                uint32_t b2b[2] = {__float_as_uint(y.z), __float_as_uint(y.w)};
                mma_tf32(o[dt], a4[0], b2a);
                mma_tf32(o[dt], a4[1], b2b);
            }
        }
        float ra, rb;
        upk2(rsA, ra, rb);
        float rs0 = ra + rb;
        upk2(rsB, ra, rb);
        float rs1 = ra + rb;
        rs0 += __shfl_xor_sync(0xffffffffu, rs0, 1);
        rs0 += __shfl_xor_sync(0xffffffffu, rs0, 2);
        rs1 += __shfl_xor_sync(0xffffffffu, rs1, 1);
        rs1 += __shfl_xor_sync(0xffffffffu, rs1, 2);
        l0 += rs0;
        l1 += rs1;
    }

    const float inv0 = 1.0f / l0, inv1 = 1.0f / l1;
    float* Cg = g_CTX + ((size_t)(b * N_SEQ + s0 + q0)) * D_MODEL + h * D_HEAD;
    #pragma unroll
    for (int dt = 0; dt < 8; dt++) {
        const int cc = dt * 8 + 2 * t;
        *(float2*)(Cg + (size_t)g * D_MODEL + cc) = make_float2(
            __uint_as_float(f2tf32(o[dt][0] * inv0)),
            __uint_as_float(f2tf32(o[dt][1] * inv0)));
        *(float2*)(Cg + (size_t)(g + 8) * D_MODEL + cc) = make_float2(
            __uint_as_float(f2tf32(o[dt][2] * inv1)),
            __uint_as_float(f2tf32(o[dt][3] * inv1)));
    }
}

// ---------------------------------------------------------------------------
extern "C" void kernel_launch(void* const* d_in, const int* in_sizes, int n_in,
                              void* d_out, int out_size)
{
    (void)in_sizes; (void)n_in; (void)out_size;
    const float* q  = (const float*)d_in[0];
    const float* k  = (const float*)d_in[1];
    const float* v  = (const float*)d_in[2];
    const float* Wq = (const float*)d_in[3];
    const float* bq = (const float*)d_in[4];
    const float* Wk = (const float*)d_in[5];
    const float* bk = (const float*)d_in[6];
    const float* Wv = (const float*)d_in[7];
    const float* bv = (const float*)d_in[8];
    const float* Wo = (const float*)d_in[9];
    const float* bo = (const float*)d_in[10];
    float* out = (float*)d_out;

    float *Qd, *K0, *V0, *Kp, *Vp, *Cd, *qc, *kc, *vc, *Wqc, *Wkc, *Wvc, *Woc;
    cudaGetSymbolAddress((void**)&Qd,  g_Q);
    cudaGetSymbolAddress((void**)&K0,  g_K0);
    cudaGetSymbolAddress((void**)&V0,  g_V0);
    cudaGetSymbolAddress((void**)&Kp,  g_Kp);
    cudaGetSymbolAddress((void**)&Vp,  g_Vp);
    cudaGetSymbolAddress((void**)&Cd,  g_CTX);
    cudaGetSymbolAddress((void**)&qc,  g_qc);
    cudaGetSymbolAddress((void**)&kc,  g_kc);
    cudaGetSymbolAddress((void**)&vc,  g_vc);
    cudaGetSymbolAddress((void**)&Wqc, g_Wqc);
    cudaGetSymbolAddress((void**)&Wkc, g_Wkc);
    cudaGetSymbolAddress((void**)&Wvc, g_Wvc);
    cudaGetSymbolAddress((void**)&Woc, g_Woc);

    cudaFuncSetAttribute(gemm_bias_kernel,
                         cudaFuncAttributeMaxDynamicSharedMemorySize, GEMM_SMEM);
    cudaFuncSetAttribute(attn_kernel,
                         cudaFuncAttributeMaxDynamicSharedMemorySize, ATTN_SMEM);

    // attn stays launch #4 (the slot ncu captures).
    prep_kernel<<<dim3(1024, 1, 7), 256>>>(              // #1
        (const float4*)q, (float4*)qc, (const float4*)k, (float4*)kc,
        (const float4*)v, (float4*)vc,
        (const float4*)Wq, (float4*)Wqc, (const float4*)Wk, (float4*)Wkc,
        (const float4*)Wv, (float4*)Wvc, (const float4*)Wo, (float4*)Woc);

    GemmSet sq{qc, Wqc, bq, Qd};
    GemmSet sk{kc, Wkc, bk, K0};
    GemmSet sv{vc, Wvc, bv, V0};
    gemm_bias_kernel<<<dim3(D_MODEL / BN, N_ROWS / BM, 3), 256, GEMM_SMEM>>>(
        sq, sk, sv, 1);                                  // #2

    pack_kv_kernel<<<dim3(128, 16, 2), 256>>>(K0, Kp, V0, Vp);   // #3

    attn_kernel<<<dim3(N_SEQ / QTILE, N_HEADS, N_BATCH), 256, ATTN_SMEM>>>();  // #4

    GemmSet so{Cd, Woc, bo, out};
    gemm_bias_kernel<<<dim3(D_MODEL / BN, N_ROWS / BM, 1), 256, GEMM_SMEM>>>(
        so, so, so, 0);                                  // #5
}